// round 3
// baseline (speedup 1.0000x reference)
#include <cuda_runtime.h>
#include <cuda_bf16.h>
#include <cstdint>

// Problem constants (fixed-shape problem; scratch sized to these)
#define N_MAX 100000
#define E_MAX 3200000

// -------------------- device scratch (no allocations allowed) --------------------
__device__ float g_agg[(size_t)N_MAX * 256];   // mean-aggregated features
__device__ float g_h[(size_t)N_MAX * 256];     // layer-0 hidden
__device__ int   g_count[N_MAX + 1];
__device__ int   g_rowptr[N_MAX + 1];
__device__ int   g_cursor[N_MAX];
__device__ float g_invdeg[N_MAX];
__device__ int   g_srcs[E_MAX];
__device__ int   g_is64;                        // edge_index dtype flag

// -------------------- dtype detection --------------------
// If edge_index is int32, interpreting as int64 fuses pairs -> huge values.
__global__ void detect_kernel(const void* ei, int Nn) {
    const long long* p = (const long long*)ei;
    int ok = 1;
    for (int i = 0; i < 64; i++) {
        long long v = p[i];
        if (v < 0 || v >= (long long)Nn) { ok = 0; break; }
    }
    g_is64 = ok;
}

__device__ __forceinline__ int load_idx(const void* ei, long long pos) {
    if (g_is64) return (int)((const long long*)ei)[pos];
    return ((const int*)ei)[pos];
}

// -------------------- CSR build --------------------
__global__ void zero_count_kernel(int n) {
    int i = blockIdx.x * blockDim.x + threadIdx.x;
    if (i <= n) g_count[i] = 0;
}

__global__ void hist_kernel(const void* __restrict__ ei, int E) {
    int e = blockIdx.x * blockDim.x + threadIdx.x;
    if (e < E) {
        int d = load_idx(ei, (long long)E + e);   // dst row
        atomicAdd(&g_count[d], 1);
    }
}

// Single-block exclusive scan over g_count -> g_rowptr/g_cursor, plus inv-degree.
__global__ void scan_kernel(int Nn, int Ee) {
    __shared__ int sums[1024];
    int t = threadIdx.x;
    int CH = (Nn + 1023) / 1024;
    int beg = t * CH;
    int end = min(beg + CH, Nn);
    int s = 0;
    for (int i = beg; i < end; i++) s += g_count[i];
    sums[t] = s;
    __syncthreads();
    for (int off = 1; off < 1024; off <<= 1) {
        int v = 0;
        if (t >= off) v = sums[t - off];
        __syncthreads();
        if (t >= off) sums[t] += v;
        __syncthreads();
    }
    int run = sums[t] - s;  // exclusive prefix for this thread's chunk
    for (int i = beg; i < end; i++) {
        int c = g_count[i];
        g_rowptr[i] = run;
        g_cursor[i] = run;
        g_invdeg[i] = 1.0f / (float)max(c, 1);
        run += c;
    }
    if (t == 1023) g_rowptr[Nn] = Ee;
}

__global__ void scatter_kernel(const void* __restrict__ ei, int E) {
    int e = blockIdx.x * blockDim.x + threadIdx.x;
    if (e < E) {
        int s = load_idx(ei, e);                  // src row
        int d = load_idx(ei, (long long)E + e);   // dst row
        int pos = atomicAdd(&g_cursor[d], 1);
        g_srcs[pos] = s;
    }
}

// -------------------- mean aggregation: one warp per node --------------------
// NPL = float4s per lane (1 -> 128 features, 2 -> 256 features)
template <int NPL>
__global__ void agg_kernel(const float4* __restrict__ X, float4* __restrict__ out, int Nn) {
    int w = (blockIdx.x * blockDim.x + threadIdx.x) >> 5;
    int lane = threadIdx.x & 31;
    if (w >= Nn) return;
    int beg = g_rowptr[w];
    int end = g_rowptr[w + 1];
    const int stride = NPL * 32;
    float4 acc[NPL];
#pragma unroll
    for (int i = 0; i < NPL; i++) acc[i] = make_float4(0.f, 0.f, 0.f, 0.f);
    for (int e = beg; e < end; e++) {
        int s = g_srcs[e];
        const float4* row = X + (size_t)s * stride;
#pragma unroll
        for (int i = 0; i < NPL; i++) {
            float4 v = __ldg(&row[lane + 32 * i]);
            acc[i].x += v.x; acc[i].y += v.y; acc[i].z += v.z; acc[i].w += v.w;
        }
    }
    float inv = g_invdeg[w];
    float4* orow = out + (size_t)w * stride;
#pragma unroll
    for (int i = 0; i < NPL; i++) {
        float4 r;
        r.x = acc[i].x * inv; r.y = acc[i].y * inv;
        r.z = acc[i].z * inv; r.w = acc[i].w * inv;
        orow[lane + 32 * i] = r;
    }
}

// -------------------- fused two-operand SGEMM --------------------
// C[M, Ncol] = act( [A1 | A2] @ [B1 ; B2] + bias )
// A1: [M, K1] (lda1), A2: [M, K2] (lda2); B1: [K1, Ncol], B2: [K2, Ncol] row-major.
// BM=BN=64, BK=16, 256 threads, 4x4 thread tile. K1, K2 multiples of 16.
#define BM 64
#define BN 64
#define BK 16

__global__ __launch_bounds__(256) void gemm_kernel(
    const float* __restrict__ A1, int lda1, int K1,
    const float* __restrict__ A2, int lda2, int K2,
    const float* __restrict__ B1, const float* __restrict__ B2,
    const float* __restrict__ bias,
    float* __restrict__ C, int ldc,
    int M, int Ncol, int do_relu)
{
    __shared__ float As[BK][BM];
    __shared__ float Bs[BK][BN];

    int tid = threadIdx.x;
    int rowbase = blockIdx.y * BM;
    int colbase = blockIdx.x * BN;

    int arow = tid >> 2;        // 0..63
    int akq  = tid & 3;         // 0..3
    int brow = tid >> 4;        // 0..15
    int bcq  = tid & 15;        // 0..15

    int ty = tid >> 4;          // 0..15
    int tx = tid & 15;          // 0..15

    float acc[4][4];
#pragma unroll
    for (int i = 0; i < 4; i++)
#pragma unroll
        for (int j = 0; j < 4; j++) acc[i][j] = 0.f;

    int K = K1 + K2;
    for (int kbase = 0; kbase < K; kbase += BK) {
        // ---- load A tile ----
        {
            const float* Ap; int lda, koff;
            if (kbase < K1) { Ap = A1; lda = lda1; koff = kbase; }
            else            { Ap = A2; lda = lda2; koff = kbase - K1; }
            int r = rowbase + arow;
            float4 v = make_float4(0.f, 0.f, 0.f, 0.f);
            if (r < M) v = *(const float4*)&Ap[(size_t)r * lda + koff + akq * 4];
            As[akq * 4 + 0][arow] = v.x;
            As[akq * 4 + 1][arow] = v.y;
            As[akq * 4 + 2][arow] = v.z;
            As[akq * 4 + 3][arow] = v.w;
        }
        // ---- load B tile ----
        {
            const float* Bp; int koff;
            if (kbase < K1) { Bp = B1; koff = kbase; }
            else            { Bp = B2; koff = kbase - K1; }
            float4 v = *(const float4*)&Bp[(size_t)(koff + brow) * Ncol + colbase + bcq * 4];
            Bs[brow][bcq * 4 + 0] = v.x;
            Bs[brow][bcq * 4 + 1] = v.y;
            Bs[brow][bcq * 4 + 2] = v.z;
            Bs[brow][bcq * 4 + 3] = v.w;
        }
        __syncthreads();

#pragma unroll
        for (int k = 0; k < BK; k++) {
            float4 a = *(const float4*)&As[k][ty * 4];
            float4 b = *(const float4*)&Bs[k][tx * 4];
            float av[4] = {a.x, a.y, a.z, a.w};
            float bv[4] = {b.x, b.y, b.z, b.w};
#pragma unroll
            for (int i = 0; i < 4; i++)
#pragma unroll
                for (int j = 0; j < 4; j++) acc[i][j] += av[i] * bv[j];
        }
        __syncthreads();
    }

    // ---- epilogue ----
    float4 bb = *(const float4*)&bias[colbase + tx * 4];
    float bv[4] = {bb.x, bb.y, bb.z, bb.w};
#pragma unroll
    for (int i = 0; i < 4; i++) {
        int r = rowbase + ty * 4 + i;
        if (r < M) {
            float4 o;
            float v0 = acc[i][0] + bv[0];
            float v1 = acc[i][1] + bv[1];
            float v2 = acc[i][2] + bv[2];
            float v3 = acc[i][3] + bv[3];
            if (do_relu) {
                v0 = fmaxf(v0, 0.f); v1 = fmaxf(v1, 0.f);
                v2 = fmaxf(v2, 0.f); v3 = fmaxf(v3, 0.f);
            }
            o.x = v0; o.y = v1; o.z = v2; o.w = v3;
            *(float4*)&C[(size_t)r * ldc + colbase + tx * 4] = o;
        }
    }
}

// -------------------- launch --------------------
extern "C" void kernel_launch(void* const* d_in, const int* in_sizes, int n_in,
                              void* d_out, int out_size) {
    const float* x   = (const float*)d_in[0];
    const void*  ei  = d_in[1];                  // int32 or int64 node ids (autodetected)
    const float* Wl0 = (const float*)d_in[2];
    const float* Wr0 = (const float*)d_in[3];
    const float* b0  = (const float*)d_in[4];
    const float* Wl1 = (const float*)d_in[5];
    const float* Wr1 = (const float*)d_in[6];
    const float* b1  = (const float*)d_in[7];
    const float* Wf  = (const float*)d_in[8];
    const float* bf  = (const float*)d_in[9];
    (void)n_in; (void)out_size;

    int Nn = in_sizes[0] / 128;   // 100000
    int Ee = in_sizes[1] / 2;     // 3200000 (element count is dtype-independent)

    float* out = (float*)d_out;                 // [N, 64]
    float* emb = out + (size_t)Nn * 64;         // [N, 256]

    void *p_agg, *p_h;
    cudaGetSymbolAddress(&p_agg, g_agg);
    cudaGetSymbolAddress(&p_h, g_h);
    float* agg = (float*)p_agg;
    float* h   = (float*)p_h;

    // 0) detect edge_index dtype (int32 vs int64)
    detect_kernel<<<1, 1>>>(ei, Nn);

    // 1) CSR build (by dst), reused for both layers
    zero_count_kernel<<<(Nn + 256) / 256, 256>>>(Nn);
    hist_kernel<<<(Ee + 255) / 256, 256>>>(ei, Ee);
    scan_kernel<<<1, 1024>>>(Nn, Ee);
    scatter_kernel<<<(Ee + 255) / 256, 256>>>(ei, Ee);

    // 2) layer 0: mean agg (128) then fused GEMM  h = relu(x@Wl0 + agg@Wr0 + b0)
    agg_kernel<1><<<(Nn + 7) / 8, 256>>>((const float4*)x, (float4*)agg, Nn);
    {
        dim3 grid(256 / BN, (Nn + BM - 1) / BM);
        gemm_kernel<<<grid, 256>>>(x, 128, 128, agg, 128, 128,
                                   Wl0, Wr0, b0, h, 256, Nn, 256, 1);
    }

    // 3) layer 1: mean agg (256) then fused GEMM  emb = relu(h@Wl1 + agg@Wr1 + b1)
    agg_kernel<2><<<(Nn + 7) / 8, 256>>>((const float4*)h, (float4*)agg, Nn);
    {
        dim3 grid(256 / BN, (Nn + BM - 1) / BM);
        gemm_kernel<<<grid, 256>>>(h, 256, 256, agg, 256, 256,
                                   Wl1, Wr1, b1, emb, 256, Nn, 256, 1);
    }

    // 4) head: out = emb @ Wf + bf
    {
        dim3 grid(64 / BN, (Nn + BM - 1) / BM);
        gemm_kernel<<<grid, 256>>>(emb, 256, 256, (const float*)nullptr, 0, 0,
                                   Wf, (const float*)nullptr, bf, out, 64, Nn, 64, 0);
    }
}

// round 4
// speedup vs baseline: 1.2298x; 1.2298x over previous
#include <cuda_runtime.h>
#include <cuda_bf16.h>
#include <cstdint>

#define N_MAX 100000
#define E_MAX 3200000
#define SCAN_BLOCKS 128
#define SCAN_THREADS 256

// -------------------- device scratch --------------------
__device__ float g_agg[(size_t)N_MAX * 256];
__device__ float g_h[(size_t)N_MAX * 256];
__device__ int   g_count[N_MAX + 1];
__device__ int   g_rowptr[N_MAX + 1];
__device__ int   g_cursor[N_MAX];
__device__ float g_invdeg[N_MAX];
__device__ int   g_srcs[E_MAX];
__device__ int   g_is64;
__device__ int   g_bsum[SCAN_BLOCKS];
__device__ int   g_boff[SCAN_BLOCKS];

// -------------------- dtype detection --------------------
__global__ void detect_kernel(const void* ei, int Nn) {
    const long long* p = (const long long*)ei;
    int ok = 1;
    for (int i = 0; i < 64; i++) {
        long long v = p[i];
        if (v < 0 || v >= (long long)Nn) { ok = 0; break; }
    }
    g_is64 = ok;
}

__device__ __forceinline__ int load_idx(const void* ei, long long pos) {
    if (g_is64) return (int)((const long long*)ei)[pos];
    return ((const int*)ei)[pos];
}

// -------------------- CSR build --------------------
__global__ void zero_count_kernel(int n) {
    int i = blockIdx.x * blockDim.x + threadIdx.x;
    if (i <= n) g_count[i] = 0;
}

__global__ void hist_kernel(const void* __restrict__ ei, int E) {
    int e = blockIdx.x * blockDim.x + threadIdx.x;
    if (e < E) atomicAdd(&g_count[load_idx(ei, (long long)E + e)], 1);
}

// ---- 3-phase parallel exclusive scan over g_count ----
__device__ __forceinline__ void chunk_bounds(int Nn, int b, int t, int& tb, int& te) {
    int chunk = (Nn + SCAN_BLOCKS - 1) / SCAN_BLOCKS;
    int bbeg = b * chunk;
    int bend = min(bbeg + chunk, Nn);
    int tCH = (chunk + SCAN_THREADS - 1) / SCAN_THREADS;
    tb = bbeg + t * tCH;
    te = min(tb + tCH, bend);
}

__global__ void scan_p1(int Nn) {
    __shared__ int sh[SCAN_THREADS];
    int b = blockIdx.x, t = threadIdx.x;
    int tb, te; chunk_bounds(Nn, b, t, tb, te);
    int s = 0;
    for (int i = tb; i < te; i++) s += g_count[i];
    sh[t] = s;
    __syncthreads();
    for (int off = SCAN_THREADS / 2; off > 0; off >>= 1) {
        if (t < off) sh[t] += sh[t + off];
        __syncthreads();
    }
    if (t == 0) g_bsum[b] = sh[0];
}

__global__ void scan_p2(int Ee, int Nn) {
    __shared__ int sh[SCAN_BLOCKS];
    int t = threadIdx.x;
    int v = (t < SCAN_BLOCKS) ? g_bsum[t] : 0;
    if (t < SCAN_BLOCKS) sh[t] = v;
    __syncthreads();
    for (int off = 1; off < SCAN_BLOCKS; off <<= 1) {
        int u = 0;
        if (t < SCAN_BLOCKS && t >= off) u = sh[t - off];
        __syncthreads();
        if (t < SCAN_BLOCKS && t >= off) sh[t] += u;
        __syncthreads();
    }
    if (t < SCAN_BLOCKS) g_boff[t] = sh[t] - v;  // exclusive
    if (t == 0) g_rowptr[Nn] = Ee;
}

__global__ void scan_p3(int Nn) {
    __shared__ int sh[SCAN_THREADS];
    int b = blockIdx.x, t = threadIdx.x;
    int tb, te; chunk_bounds(Nn, b, t, tb, te);
    int s = 0;
    for (int i = tb; i < te; i++) s += g_count[i];
    sh[t] = s;
    __syncthreads();
    for (int off = 1; off < SCAN_THREADS; off <<= 1) {
        int u = 0;
        if (t >= off) u = sh[t - off];
        __syncthreads();
        if (t >= off) sh[t] += u;
        __syncthreads();
    }
    int run = sh[t] - s + g_boff[b];  // exclusive prefix for this thread
    for (int i = tb; i < te; i++) {
        int c = g_count[i];
        g_rowptr[i] = run;
        g_cursor[i] = run;
        g_invdeg[i] = 1.0f / (float)max(c, 1);
        run += c;
    }
}

__global__ void scatter_kernel(const void* __restrict__ ei, int E) {
    int e = blockIdx.x * blockDim.x + threadIdx.x;
    if (e < E) {
        int s = load_idx(ei, e);
        int d = load_idx(ei, (long long)E + e);
        int pos = atomicAdd(&g_cursor[d], 1);
        g_srcs[pos] = s;
    }
}

// -------------------- mean aggregation: one warp per node --------------------
template <int NPL>
__global__ void agg_kernel(const float4* __restrict__ X, float4* __restrict__ out, int Nn) {
    int w = (blockIdx.x * blockDim.x + threadIdx.x) >> 5;
    int lane = threadIdx.x & 31;
    if (w >= Nn) return;
    int beg = g_rowptr[w];
    int end = g_rowptr[w + 1];
    const int stride = NPL * 32;
    float4 acc[NPL];
#pragma unroll
    for (int i = 0; i < NPL; i++) acc[i] = make_float4(0.f, 0.f, 0.f, 0.f);
    for (int e = beg; e < end; e++) {
        int s = g_srcs[e];
        const float4* row = X + (size_t)s * stride;
#pragma unroll
        for (int i = 0; i < NPL; i++) {
            float4 v = __ldg(&row[lane + 32 * i]);
            acc[i].x += v.x; acc[i].y += v.y; acc[i].z += v.z; acc[i].w += v.w;
        }
    }
    float inv = g_invdeg[w];
    float4* orow = out + (size_t)w * stride;
#pragma unroll
    for (int i = 0; i < NPL; i++) {
        float4 r;
        r.x = acc[i].x * inv; r.y = acc[i].y * inv;
        r.z = acc[i].z * inv; r.w = acc[i].w * inv;
        orow[lane + 32 * i] = r;
    }
}

// -------------------- 128x128x16 SGEMM, 8x8 per thread --------------------
// C[M, Ncol] = act( [A1 | A2] @ [B1 ; B2] + bias ), Ncol multiple of 128.
#define GBM 128
#define GBN 128
#define GBK 16

__global__ __launch_bounds__(256) void gemm128_kernel(
    const float* __restrict__ A1, int lda1, int K1,
    const float* __restrict__ A2, int lda2, int K2,
    const float* __restrict__ B1, const float* __restrict__ B2,
    const float* __restrict__ bias,
    float* __restrict__ C, int ldc,
    int M, int Ncol, int do_relu)
{
    __shared__ float As[GBK][GBM];
    __shared__ float Bs[GBK][GBN];

    int tid = threadIdx.x;
    int rowbase = blockIdx.y * GBM;
    int colbase = blockIdx.x * GBN;

    int ty = tid >> 4;   // 0..15 -> rows ty*8..ty*8+7
    int tx = tid & 15;   // 0..15 -> cols tx*8..tx*8+7

    float acc[8][8];
#pragma unroll
    for (int i = 0; i < 8; i++)
#pragma unroll
        for (int j = 0; j < 8; j++) acc[i][j] = 0.f;

    int K = K1 + K2;
    for (int kbase = 0; kbase < K; kbase += GBK) {
        // ---- load A tile: 128 rows x 16 cols = 512 float4, 2 per thread ----
        {
            const float* Ap; int lda, koff;
            if (kbase < K1) { Ap = A1; lda = lda1; koff = kbase; }
            else            { Ap = A2; lda = lda2; koff = kbase - K1; }
#pragma unroll
            for (int it = 0; it < 2; it++) {
                int idx = tid * 2 + it;
                int row = idx >> 2;         // 0..127
                int q   = idx & 3;          // float4 within 16-wide K
                int r = rowbase + row;
                float4 v = make_float4(0.f, 0.f, 0.f, 0.f);
                if (r < M) v = *(const float4*)&Ap[(size_t)r * lda + koff + q * 4];
                As[q * 4 + 0][row] = v.x;
                As[q * 4 + 1][row] = v.y;
                As[q * 4 + 2][row] = v.z;
                As[q * 4 + 3][row] = v.w;
            }
        }
        // ---- load B tile: 16 rows x 128 cols = 512 float4, 2 per thread ----
        {
            const float* Bp; int koff;
            if (kbase < K1) { Bp = B1; koff = kbase; }
            else            { Bp = B2; koff = kbase - K1; }
#pragma unroll
            for (int it = 0; it < 2; it++) {
                int idx = tid * 2 + it;
                int row = idx >> 5;         // 0..15
                int q   = idx & 31;         // float4 within 128-wide N
                float4 v = *(const float4*)&Bp[(size_t)(koff + row) * Ncol + colbase + q * 4];
                *(float4*)&Bs[row][q * 4] = v;
            }
        }
        __syncthreads();

#pragma unroll
        for (int k = 0; k < GBK; k++) {
            float a[8], bvv[8];
            *(float4*)&a[0]   = *(const float4*)&As[k][ty * 8];
            *(float4*)&a[4]   = *(const float4*)&As[k][ty * 8 + 4];
            *(float4*)&bvv[0] = *(const float4*)&Bs[k][tx * 8];
            *(float4*)&bvv[4] = *(const float4*)&Bs[k][tx * 8 + 4];
#pragma unroll
            for (int i = 0; i < 8; i++)
#pragma unroll
                for (int j = 0; j < 8; j++) acc[i][j] += a[i] * bvv[j];
        }
        __syncthreads();
    }

    // ---- epilogue ----
    float bv[8];
    *(float4*)&bv[0] = *(const float4*)&bias[colbase + tx * 8];
    *(float4*)&bv[4] = *(const float4*)&bias[colbase + tx * 8 + 4];
#pragma unroll
    for (int i = 0; i < 8; i++) {
        int r = rowbase + ty * 8 + i;
        if (r < M) {
            float o[8];
#pragma unroll
            for (int j = 0; j < 8; j++) {
                float v = acc[i][j] + bv[j];
                o[j] = do_relu ? fmaxf(v, 0.f) : v;
            }
            *(float4*)&C[(size_t)r * ldc + colbase + tx * 8]     = *(float4*)&o[0];
            *(float4*)&C[(size_t)r * ldc + colbase + tx * 8 + 4] = *(float4*)&o[4];
        }
    }
}

// -------------------- 64x64x16 SGEMM (head, N=64) --------------------
#define BM 64
#define BN 64
#define BK 16

__global__ __launch_bounds__(256) void gemm_kernel(
    const float* __restrict__ A1, int lda1, int K1,
    const float* __restrict__ B1,
    const float* __restrict__ bias,
    float* __restrict__ C, int ldc,
    int M, int Ncol)
{
    __shared__ float As[BK][BM];
    __shared__ float Bs[BK][BN];

    int tid = threadIdx.x;
    int rowbase = blockIdx.y * BM;
    int colbase = blockIdx.x * BN;

    int arow = tid >> 2, akq = tid & 3;
    int brow = tid >> 4, bcq = tid & 15;
    int ty = tid >> 4, tx = tid & 15;

    float acc[4][4];
#pragma unroll
    for (int i = 0; i < 4; i++)
#pragma unroll
        for (int j = 0; j < 4; j++) acc[i][j] = 0.f;

    for (int kbase = 0; kbase < K1; kbase += BK) {
        {
            int r = rowbase + arow;
            float4 v = make_float4(0.f, 0.f, 0.f, 0.f);
            if (r < M) v = *(const float4*)&A1[(size_t)r * lda1 + kbase + akq * 4];
            As[akq * 4 + 0][arow] = v.x;
            As[akq * 4 + 1][arow] = v.y;
            As[akq * 4 + 2][arow] = v.z;
            As[akq * 4 + 3][arow] = v.w;
        }
        {
            float4 v = *(const float4*)&B1[(size_t)(kbase + brow) * Ncol + colbase + bcq * 4];
            *(float4*)&Bs[brow][bcq * 4] = v;
        }
        __syncthreads();
#pragma unroll
        for (int k = 0; k < BK; k++) {
            float4 a = *(const float4*)&As[k][ty * 4];
            float4 b = *(const float4*)&Bs[k][tx * 4];
            float av[4] = {a.x, a.y, a.z, a.w};
            float bvv[4] = {b.x, b.y, b.z, b.w};
#pragma unroll
            for (int i = 0; i < 4; i++)
#pragma unroll
                for (int j = 0; j < 4; j++) acc[i][j] += av[i] * bvv[j];
        }
        __syncthreads();
    }

    float4 bb = *(const float4*)&bias[colbase + tx * 4];
    float bv[4] = {bb.x, bb.y, bb.z, bb.w};
#pragma unroll
    for (int i = 0; i < 4; i++) {
        int r = rowbase + ty * 4 + i;
        if (r < M) {
            float4 o;
            o.x = acc[i][0] + bv[0];
            o.y = acc[i][1] + bv[1];
            o.z = acc[i][2] + bv[2];
            o.w = acc[i][3] + bv[3];
            *(float4*)&C[(size_t)r * ldc + colbase + tx * 4] = o;
        }
    }
}

// -------------------- launch --------------------
extern "C" void kernel_launch(void* const* d_in, const int* in_sizes, int n_in,
                              void* d_out, int out_size) {
    const float* x   = (const float*)d_in[0];
    const void*  ei  = d_in[1];
    const float* Wl0 = (const float*)d_in[2];
    const float* Wr0 = (const float*)d_in[3];
    const float* b0  = (const float*)d_in[4];
    const float* Wl1 = (const float*)d_in[5];
    const float* Wr1 = (const float*)d_in[6];
    const float* b1  = (const float*)d_in[7];
    const float* Wf  = (const float*)d_in[8];
    const float* bf  = (const float*)d_in[9];
    (void)n_in; (void)out_size;

    int Nn = in_sizes[0] / 128;   // 100000
    int Ee = in_sizes[1] / 2;     // 3200000

    float* out = (float*)d_out;                 // [N, 64]
    float* emb = out + (size_t)Nn * 64;         // [N, 256]

    void *p_agg, *p_h;
    cudaGetSymbolAddress(&p_agg, g_agg);
    cudaGetSymbolAddress(&p_h, g_h);
    float* agg = (float*)p_agg;
    float* h   = (float*)p_h;

    // 0) dtype detect
    detect_kernel<<<1, 1>>>(ei, Nn);

    // 1) CSR build (by dst)
    zero_count_kernel<<<(Nn + 256) / 256, 256>>>(Nn);
    hist_kernel<<<(Ee + 255) / 256, 256>>>(ei, Ee);
    scan_p1<<<SCAN_BLOCKS, SCAN_THREADS>>>(Nn);
    scan_p2<<<1, SCAN_BLOCKS>>>(Ee, Nn);
    scan_p3<<<SCAN_BLOCKS, SCAN_THREADS>>>(Nn);
    scatter_kernel<<<(Ee + 255) / 256, 256>>>(ei, Ee);

    // 2) layer 0
    agg_kernel<1><<<(Nn + 7) / 8, 256>>>((const float4*)x, (float4*)agg, Nn);
    {
        dim3 grid(256 / GBN, (Nn + GBM - 1) / GBM);
        gemm128_kernel<<<grid, 256>>>(x, 128, 128, agg, 128, 128,
                                      Wl0, Wr0, b0, h, 256, Nn, 256, 1);
    }

    // 3) layer 1
    agg_kernel<2><<<(Nn + 7) / 8, 256>>>((const float4*)h, (float4*)agg, Nn);
    {
        dim3 grid(256 / GBN, (Nn + GBM - 1) / GBM);
        gemm128_kernel<<<grid, 256>>>(h, 256, 256, agg, 256, 256,
                                      Wl1, Wr1, b1, emb, 256, Nn, 256, 1);
    }

    // 4) head: out = emb @ Wf + bf
    {
        dim3 grid(64 / BN, (Nn + BM - 1) / BM);
        gemm_kernel<<<grid, 256>>>(emb, 256, 256, Wf, bf, out, 64, Nn, 64);
    }
}

// round 5
// speedup vs baseline: 1.6447x; 1.3374x over previous
#include <cuda_runtime.h>
#include <cuda_bf16.h>
#include <cstdint>

#define N_MAX 100000
#define E_MAX 3200000
#define SCAN_BLOCKS 128
#define SCAN_THREADS 256

// -------------------- device scratch --------------------
__device__ float g_agg[(size_t)N_MAX * 256];
__device__ float g_h[(size_t)N_MAX * 256];
__device__ int   g_count[N_MAX + 1];
__device__ int   g_rowptr[N_MAX + 1];
__device__ int   g_cursor[N_MAX];
__device__ float g_invdeg[N_MAX];
__device__ int   g_srcs[E_MAX];
__device__ int   g_is64;
__device__ int   g_bsum[SCAN_BLOCKS];
__device__ int   g_boff[SCAN_BLOCKS];

// -------------------- dtype detection --------------------
__global__ void detect_kernel(const void* ei, int Nn) {
    const long long* p = (const long long*)ei;
    int ok = 1;
    for (int i = 0; i < 64; i++) {
        long long v = p[i];
        if (v < 0 || v >= (long long)Nn) { ok = 0; break; }
    }
    g_is64 = ok;
}

__device__ __forceinline__ int load_idx(const void* ei, long long pos) {
    if (g_is64) return (int)((const long long*)ei)[pos];
    return ((const int*)ei)[pos];
}

// -------------------- CSR build --------------------
__global__ void zero_count_kernel(int n) {
    int i = blockIdx.x * blockDim.x + threadIdx.x;
    if (i <= n) g_count[i] = 0;
}

__global__ void hist_kernel(const void* __restrict__ ei, int E) {
    int e = blockIdx.x * blockDim.x + threadIdx.x;
    if (e < E) atomicAdd(&g_count[load_idx(ei, (long long)E + e)], 1);
}

__device__ __forceinline__ void chunk_bounds(int Nn, int b, int t, int& tb, int& te) {
    int chunk = (Nn + SCAN_BLOCKS - 1) / SCAN_BLOCKS;
    int bbeg = b * chunk;
    int bend = min(bbeg + chunk, Nn);
    int tCH = (chunk + SCAN_THREADS - 1) / SCAN_THREADS;
    tb = bbeg + t * tCH;
    te = min(tb + tCH, bend);
}

__global__ void scan_p1(int Nn) {
    __shared__ int sh[SCAN_THREADS];
    int b = blockIdx.x, t = threadIdx.x;
    int tb, te; chunk_bounds(Nn, b, t, tb, te);
    int s = 0;
    for (int i = tb; i < te; i++) s += g_count[i];
    sh[t] = s;
    __syncthreads();
    for (int off = SCAN_THREADS / 2; off > 0; off >>= 1) {
        if (t < off) sh[t] += sh[t + off];
        __syncthreads();
    }
    if (t == 0) g_bsum[b] = sh[0];
}

__global__ void scan_p2(int Ee, int Nn) {
    __shared__ int sh[SCAN_BLOCKS];
    int t = threadIdx.x;
    int v = (t < SCAN_BLOCKS) ? g_bsum[t] : 0;
    if (t < SCAN_BLOCKS) sh[t] = v;
    __syncthreads();
    for (int off = 1; off < SCAN_BLOCKS; off <<= 1) {
        int u = 0;
        if (t < SCAN_BLOCKS && t >= off) u = sh[t - off];
        __syncthreads();
        if (t < SCAN_BLOCKS && t >= off) sh[t] += u;
        __syncthreads();
    }
    if (t < SCAN_BLOCKS) g_boff[t] = sh[t] - v;
    if (t == 0) g_rowptr[Nn] = Ee;
}

__global__ void scan_p3(int Nn) {
    __shared__ int sh[SCAN_THREADS];
    int b = blockIdx.x, t = threadIdx.x;
    int tb, te; chunk_bounds(Nn, b, t, tb, te);
    int s = 0;
    for (int i = tb; i < te; i++) s += g_count[i];
    sh[t] = s;
    __syncthreads();
    for (int off = 1; off < SCAN_THREADS; off <<= 1) {
        int u = 0;
        if (t >= off) u = sh[t - off];
        __syncthreads();
        if (t >= off) sh[t] += u;
        __syncthreads();
    }
    int run = sh[t] - s + g_boff[b];
    for (int i = tb; i < te; i++) {
        int c = g_count[i];
        g_rowptr[i] = run;
        g_cursor[i] = run;
        g_invdeg[i] = 1.0f / (float)max(c, 1);
        run += c;
    }
}

__global__ void scatter_kernel(const void* __restrict__ ei, int E) {
    int e = blockIdx.x * blockDim.x + threadIdx.x;
    if (e < E) {
        int s = load_idx(ei, e);
        int d = load_idx(ei, (long long)E + e);
        int pos = atomicAdd(&g_cursor[d], 1);
        g_srcs[pos] = s;
    }
}

// -------------------- mean aggregation: one warp per node --------------------
template <int NPL>
__global__ void agg_kernel(const float4* __restrict__ X, float4* __restrict__ out, int Nn) {
    int w = (blockIdx.x * blockDim.x + threadIdx.x) >> 5;
    int lane = threadIdx.x & 31;
    if (w >= Nn) return;
    int beg = g_rowptr[w];
    int end = g_rowptr[w + 1];
    const int stride = NPL * 32;
    float4 acc[NPL];
#pragma unroll
    for (int i = 0; i < NPL; i++) acc[i] = make_float4(0.f, 0.f, 0.f, 0.f);
    for (int e = beg; e < end; e++) {
        int s = g_srcs[e];
        const float4* row = X + (size_t)s * stride;
#pragma unroll
        for (int i = 0; i < NPL; i++) {
            float4 v = __ldg(&row[lane + 32 * i]);
            acc[i].x += v.x; acc[i].y += v.y; acc[i].z += v.z; acc[i].w += v.w;
        }
    }
    float inv = g_invdeg[w];
    float4* orow = out + (size_t)w * stride;
#pragma unroll
    for (int i = 0; i < NPL; i++) {
        float4 r;
        r.x = acc[i].x * inv; r.y = acc[i].y * inv;
        r.z = acc[i].z * inv; r.w = acc[i].w * inv;
        orow[lane + 32 * i] = r;
    }
}

// -------------------- TF32 tensor-core GEMM (mma.sync m16n8k8) --------------------
// C[M, Ncol] = act( [A1 | A2] @ [B1 ; B2] + bias ), Ncol multiple of 128,
// K1/K2 multiples of 32. Block tile 128x128x32, 8 warps, warp tile 32x64.

#define TBM 128
#define TBN 128
#define TBK 32
#define KSTR 36   // k-minor smem stride (floats); 4*grp+q hits all 32 banks

__device__ __forceinline__ uint32_t f2tf32(float f) {
    uint32_t u;
    asm("cvt.rna.tf32.f32 %0, %1;" : "=r"(u) : "f"(f));
    return u;
}

__device__ __forceinline__ void mma_tf32(float c[4],
                                         uint32_t a0, uint32_t a1, uint32_t a2, uint32_t a3,
                                         uint32_t b0, uint32_t b1) {
    asm volatile(
        "mma.sync.aligned.m16n8k8.row.col.f32.tf32.tf32.f32 "
        "{%0,%1,%2,%3}, {%4,%5,%6,%7}, {%8,%9}, {%0,%1,%2,%3};"
        : "+f"(c[0]), "+f"(c[1]), "+f"(c[2]), "+f"(c[3])
        : "r"(a0), "r"(a1), "r"(a2), "r"(a3), "r"(b0), "r"(b1));
}

__global__ __launch_bounds__(256) void gemm_tf32_kernel(
    const float* __restrict__ A1, int lda1, int K1,
    const float* __restrict__ A2, int lda2, int K2,
    const float* __restrict__ B1, const float* __restrict__ B2,
    const float* __restrict__ bias,
    float* __restrict__ C, int ldc,
    int M, int Ncol, int do_relu)
{
    __shared__ uint32_t As[TBM][KSTR];  // [m][k], tf32 bits
    __shared__ uint32_t Bs[TBN][KSTR];  // [n][k], tf32 bits

    int tid = threadIdx.x;
    int lane = tid & 31;
    int wid = tid >> 5;
    int grp = lane >> 2;       // 0..7
    int q = lane & 3;          // 0..3
    int warp_m = (wid & 3) * 32;
    int warp_n = (wid >> 2) * 64;
    int rowbase = blockIdx.y * TBM;
    int colbase = blockIdx.x * TBN;

    float acc[2][8][4];
#pragma unroll
    for (int mt = 0; mt < 2; mt++)
#pragma unroll
        for (int nt = 0; nt < 8; nt++)
#pragma unroll
            for (int r = 0; r < 4; r++) acc[mt][nt][r] = 0.f;

    int K = K1 + K2;
    for (int kbase = 0; kbase < K; kbase += TBK) {
        const float* Ap; const float* Bp; int lda, koff;
        if (kbase < K1) { Ap = A1; lda = lda1; Bp = B1; koff = kbase; }
        else            { Ap = A2; lda = lda2; Bp = B2; koff = kbase - K1; }

        // ---- A: 128x32 floats = 1024 float4, 4 per thread ----
#pragma unroll
        for (int it = 0; it < 4; it++) {
            int idx = tid + it * 256;
            int row = idx >> 3;
            int kq = (idx & 7) * 4;
            int r = rowbase + row;
            float4 v = make_float4(0.f, 0.f, 0.f, 0.f);
            if (r < M) v = *(const float4*)&Ap[(size_t)r * lda + koff + kq];
            uint4 u;
            u.x = f2tf32(v.x); u.y = f2tf32(v.y);
            u.z = f2tf32(v.z); u.w = f2tf32(v.w);
            *(uint4*)&As[row][kq] = u;
        }
        // ---- B: 32x128 floats, transposed into Bs[n][k] ----
#pragma unroll
        for (int it = 0; it < 4; it++) {
            int idx = tid + it * 256;
            int krow = idx >> 5;
            int nq = (idx & 31) * 4;
            float4 v = *(const float4*)&Bp[(size_t)(koff + krow) * Ncol + colbase + nq];
            Bs[nq + 0][krow] = f2tf32(v.x);
            Bs[nq + 1][krow] = f2tf32(v.y);
            Bs[nq + 2][krow] = f2tf32(v.z);
            Bs[nq + 3][krow] = f2tf32(v.w);
        }
        __syncthreads();

#pragma unroll
        for (int kc = 0; kc < TBK; kc += 8) {
            uint32_t a[2][4];
#pragma unroll
            for (int mt = 0; mt < 2; mt++) {
                int r = warp_m + mt * 16 + grp;
                a[mt][0] = As[r][kc + q];
                a[mt][1] = As[r + 8][kc + q];
                a[mt][2] = As[r][kc + q + 4];
                a[mt][3] = As[r + 8][kc + q + 4];
            }
#pragma unroll
            for (int nt = 0; nt < 8; nt++) {
                int c = warp_n + nt * 8 + grp;
                uint32_t b0 = Bs[c][kc + q];
                uint32_t b1 = Bs[c][kc + q + 4];
#pragma unroll
                for (int mt = 0; mt < 2; mt++)
                    mma_tf32(acc[mt][nt], a[mt][0], a[mt][1], a[mt][2], a[mt][3], b0, b1);
            }
        }
        __syncthreads();
    }

    // ---- epilogue ----
#pragma unroll
    for (int nt = 0; nt < 8; nt++) {
        int ccol = colbase + warp_n + nt * 8 + q * 2;
        float bv0 = bias[ccol];
        float bv1 = bias[ccol + 1];
#pragma unroll
        for (int mt = 0; mt < 2; mt++) {
            int r0 = rowbase + warp_m + mt * 16 + grp;
            int r1 = r0 + 8;
            float v0 = acc[mt][nt][0] + bv0;
            float v1 = acc[mt][nt][1] + bv1;
            float v2 = acc[mt][nt][2] + bv0;
            float v3 = acc[mt][nt][3] + bv1;
            if (do_relu) {
                v0 = fmaxf(v0, 0.f); v1 = fmaxf(v1, 0.f);
                v2 = fmaxf(v2, 0.f); v3 = fmaxf(v3, 0.f);
            }
            if (r0 < M) { float2 o = {v0, v1}; *(float2*)&C[(size_t)r0 * ldc + ccol] = o; }
            if (r1 < M) { float2 o = {v2, v3}; *(float2*)&C[(size_t)r1 * ldc + ccol] = o; }
        }
    }
}

// -------------------- 64x64x16 SGEMM (head, N=64) --------------------
#define BM 64
#define BN 64
#define BK 16

__global__ __launch_bounds__(256) void gemm_kernel(
    const float* __restrict__ A1, int lda1, int K1,
    const float* __restrict__ B1,
    const float* __restrict__ bias,
    float* __restrict__ C, int ldc,
    int M, int Ncol)
{
    __shared__ float As[BK][BM];
    __shared__ float Bs[BK][BN];

    int tid = threadIdx.x;
    int rowbase = blockIdx.y * BM;
    int colbase = blockIdx.x * BN;

    int arow = tid >> 2, akq = tid & 3;
    int brow = tid >> 4, bcq = tid & 15;
    int ty = tid >> 4, tx = tid & 15;

    float acc[4][4];
#pragma unroll
    for (int i = 0; i < 4; i++)
#pragma unroll
        for (int j = 0; j < 4; j++) acc[i][j] = 0.f;

    for (int kbase = 0; kbase < K1; kbase += BK) {
        {
            int r = rowbase + arow;
            float4 v = make_float4(0.f, 0.f, 0.f, 0.f);
            if (r < M) v = *(const float4*)&A1[(size_t)r * lda1 + kbase + akq * 4];
            As[akq * 4 + 0][arow] = v.x;
            As[akq * 4 + 1][arow] = v.y;
            As[akq * 4 + 2][arow] = v.z;
            As[akq * 4 + 3][arow] = v.w;
        }
        {
            float4 v = *(const float4*)&B1[(size_t)(kbase + brow) * Ncol + colbase + bcq * 4];
            *(float4*)&Bs[brow][bcq * 4] = v;
        }
        __syncthreads();
#pragma unroll
        for (int k = 0; k < BK; k++) {
            float4 a = *(const float4*)&As[k][ty * 4];
            float4 b = *(const float4*)&Bs[k][tx * 4];
            float av[4] = {a.x, a.y, a.z, a.w};
            float bvv[4] = {b.x, b.y, b.z, b.w};
#pragma unroll
            for (int i = 0; i < 4; i++)
#pragma unroll
                for (int j = 0; j < 4; j++) acc[i][j] += av[i] * bvv[j];
        }
        __syncthreads();
    }

    float4 bb = *(const float4*)&bias[colbase + tx * 4];
    float bv[4] = {bb.x, bb.y, bb.z, bb.w};
#pragma unroll
    for (int i = 0; i < 4; i++) {
        int r = rowbase + ty * 4 + i;
        if (r < M) {
            float4 o;
            o.x = acc[i][0] + bv[0];
            o.y = acc[i][1] + bv[1];
            o.z = acc[i][2] + bv[2];
            o.w = acc[i][3] + bv[3];
            *(float4*)&C[(size_t)r * ldc + colbase + tx * 4] = o;
        }
    }
}

// -------------------- launch --------------------
extern "C" void kernel_launch(void* const* d_in, const int* in_sizes, int n_in,
                              void* d_out, int out_size) {
    const float* x   = (const float*)d_in[0];
    const void*  ei  = d_in[1];
    const float* Wl0 = (const float*)d_in[2];
    const float* Wr0 = (const float*)d_in[3];
    const float* b0  = (const float*)d_in[4];
    const float* Wl1 = (const float*)d_in[5];
    const float* Wr1 = (const float*)d_in[6];
    const float* b1  = (const float*)d_in[7];
    const float* Wf  = (const float*)d_in[8];
    const float* bf  = (const float*)d_in[9];
    (void)n_in; (void)out_size;

    int Nn = in_sizes[0] / 128;   // 100000
    int Ee = in_sizes[1] / 2;     // 3200000

    float* out = (float*)d_out;                 // [N, 64]
    float* emb = out + (size_t)Nn * 64;         // [N, 256]

    void *p_agg, *p_h;
    cudaGetSymbolAddress(&p_agg, g_agg);
    cudaGetSymbolAddress(&p_h, g_h);
    float* agg = (float*)p_agg;
    float* h   = (float*)p_h;

    // 0) dtype detect
    detect_kernel<<<1, 1>>>(ei, Nn);

    // 1) CSR build (by dst)
    zero_count_kernel<<<(Nn + 256) / 256, 256>>>(Nn);
    hist_kernel<<<(Ee + 255) / 256, 256>>>(ei, Ee);
    scan_p1<<<SCAN_BLOCKS, SCAN_THREADS>>>(Nn);
    scan_p2<<<1, SCAN_BLOCKS>>>(Ee, Nn);
    scan_p3<<<SCAN_BLOCKS, SCAN_THREADS>>>(Nn);
    scatter_kernel<<<(Ee + 255) / 256, 256>>>(ei, Ee);

    // 2) layer 0: h = relu(x@Wl0 + agg@Wr0 + b0)
    agg_kernel<1><<<(Nn + 7) / 8, 256>>>((const float4*)x, (float4*)agg, Nn);
    {
        dim3 grid(256 / TBN, (Nn + TBM - 1) / TBM);
        gemm_tf32_kernel<<<grid, 256>>>(x, 128, 128, agg, 128, 128,
                                        Wl0, Wr0, b0, h, 256, Nn, 256, 1);
    }

    // 3) layer 1: emb = relu(h@Wl1 + agg@Wr1 + b1)
    agg_kernel<2><<<(Nn + 7) / 8, 256>>>((const float4*)h, (float4*)agg, Nn);
    {
        dim3 grid(256 / TBN, (Nn + TBM - 1) / TBM);
        gemm_tf32_kernel<<<grid, 256>>>(h, 256, 256, agg, 256, 256,
                                        Wl1, Wr1, b1, emb, 256, Nn, 256, 1);
    }

    // 4) head: out = emb @ Wf + bf
    {
        dim3 grid(64 / BN, (Nn + BM - 1) / BM);
        gemm_kernel<<<grid, 256>>>(emb, 256, 256, Wf, bf, out, 64, Nn, 64);
    }
}

// round 6
// speedup vs baseline: 1.8169x; 1.1047x over previous
#include <cuda_runtime.h>
#include <cuda_bf16.h>
#include <cstdint>

#define N_MAX 100000
#define E_MAX 3200000
#define SCAN_BLOCKS 128
#define SCAN_THREADS 256

// -------------------- device scratch --------------------
__device__ float g_agg[(size_t)N_MAX * 256];
__device__ float g_h[(size_t)N_MAX * 256];
__device__ int   g_count[N_MAX + 1];
__device__ int   g_rowptr[N_MAX + 1];
__device__ int   g_cursor[N_MAX];
__device__ float g_invdeg[N_MAX];
__device__ int   g_srcs[E_MAX];
__device__ int   g_is64;
__device__ int   g_bsum[SCAN_BLOCKS];
__device__ int   g_boff[SCAN_BLOCKS];

// -------------------- dtype detection (parallel) --------------------
__global__ void detect_kernel(const void* ei, int Nn) {
    const long long* p = (const long long*)ei;
    int t = threadIdx.x;
    long long v = p[t];
    int bad = (v < 0 || v >= (long long)Nn);
    unsigned m = __ballot_sync(0xFFFFFFFFu, bad);
    __shared__ unsigned sm[2];
    if ((t & 31) == 0) sm[t >> 5] = m;
    __syncthreads();
    if (t == 0) g_is64 = (sm[0] | sm[1]) == 0u;
}

__device__ __forceinline__ int load_idx(const void* ei, long long pos) {
    if (g_is64) return (int)((const long long*)ei)[pos];
    return ((const int*)ei)[pos];
}

// -------------------- CSR build --------------------
__global__ void zero_count_kernel(int n) {
    int i = blockIdx.x * blockDim.x + threadIdx.x;
    if (i <= n) g_count[i] = 0;
}

__global__ void hist_kernel(const void* __restrict__ ei, int E) {
    int e = blockIdx.x * blockDim.x + threadIdx.x;
    if (e < E) atomicAdd(&g_count[load_idx(ei, (long long)E + e)], 1);
}

__device__ __forceinline__ void chunk_bounds(int Nn, int b, int t, int& tb, int& te) {
    int chunk = (Nn + SCAN_BLOCKS - 1) / SCAN_BLOCKS;
    int bbeg = b * chunk;
    int bend = min(bbeg + chunk, Nn);
    int tCH = (chunk + SCAN_THREADS - 1) / SCAN_THREADS;
    tb = bbeg + t * tCH;
    te = min(tb + tCH, bend);
}

__global__ void scan_p1(int Nn) {
    __shared__ int sh[SCAN_THREADS];
    int b = blockIdx.x, t = threadIdx.x;
    int tb, te; chunk_bounds(Nn, b, t, tb, te);
    int s = 0;
    for (int i = tb; i < te; i++) s += g_count[i];
    sh[t] = s;
    __syncthreads();
    for (int off = SCAN_THREADS / 2; off > 0; off >>= 1) {
        if (t < off) sh[t] += sh[t + off];
        __syncthreads();
    }
    if (t == 0) g_bsum[b] = sh[0];
}

__global__ void scan_p2(int Ee, int Nn) {
    __shared__ int sh[SCAN_BLOCKS];
    int t = threadIdx.x;
    int v = (t < SCAN_BLOCKS) ? g_bsum[t] : 0;
    if (t < SCAN_BLOCKS) sh[t] = v;
    __syncthreads();
    for (int off = 1; off < SCAN_BLOCKS; off <<= 1) {
        int u = 0;
        if (t < SCAN_BLOCKS && t >= off) u = sh[t - off];
        __syncthreads();
        if (t < SCAN_BLOCKS && t >= off) sh[t] += u;
        __syncthreads();
    }
    if (t < SCAN_BLOCKS) g_boff[t] = sh[t] - v;
    if (t == 0) g_rowptr[Nn] = Ee;
}

__global__ void scan_p3(int Nn) {
    __shared__ int sh[SCAN_THREADS];
    int b = blockIdx.x, t = threadIdx.x;
    int tb, te; chunk_bounds(Nn, b, t, tb, te);
    int s = 0;
    for (int i = tb; i < te; i++) s += g_count[i];
    sh[t] = s;
    __syncthreads();
    for (int off = 1; off < SCAN_THREADS; off <<= 1) {
        int u = 0;
        if (t >= off) u = sh[t - off];
        __syncthreads();
        if (t >= off) sh[t] += u;
        __syncthreads();
    }
    int run = sh[t] - s + g_boff[b];
    for (int i = tb; i < te; i++) {
        int c = g_count[i];
        g_rowptr[i] = run;
        g_cursor[i] = run;
        g_invdeg[i] = 1.0f / (float)max(c, 1);
        run += c;
    }
}

__global__ void scatter_kernel(const void* __restrict__ ei, int E) {
    int e = blockIdx.x * blockDim.x + threadIdx.x;
    if (e < E) {
        int s = load_idx(ei, e);
        int d = load_idx(ei, (long long)E + e);
        int pos = atomicAdd(&g_cursor[d], 1);
        g_srcs[pos] = s;
    }
}

// -------------------- mean aggregation: one warp per node --------------------
template <int NPL>
__global__ void agg_kernel(const float4* __restrict__ X, float4* __restrict__ out, int Nn) {
    int w = (blockIdx.x * blockDim.x + threadIdx.x) >> 5;
    int lane = threadIdx.x & 31;
    if (w >= Nn) return;
    int beg = g_rowptr[w];
    int end = g_rowptr[w + 1];
    const int stride = NPL * 32;
    float4 acc[NPL];
#pragma unroll
    for (int i = 0; i < NPL; i++) acc[i] = make_float4(0.f, 0.f, 0.f, 0.f);
    for (int e = beg; e < end; e++) {
        int s = g_srcs[e];
        const float4* row = X + (size_t)s * stride;
#pragma unroll
        for (int i = 0; i < NPL; i++) {
            float4 v = __ldg(&row[lane + 32 * i]);
            acc[i].x += v.x; acc[i].y += v.y; acc[i].z += v.z; acc[i].w += v.w;
        }
    }
    float inv = g_invdeg[w];
    float4* orow = out + (size_t)w * stride;
#pragma unroll
    for (int i = 0; i < NPL; i++) {
        float4 r;
        r.x = acc[i].x * inv; r.y = acc[i].y * inv;
        r.z = acc[i].z * inv; r.w = acc[i].w * inv;
        orow[lane + 32 * i] = r;
    }
}

// -------------------- TF32 tensor-core GEMM (mma.sync m16n8k8) --------------------
// Block tile 128 x TBN x 32, 8 warps (4 in M x 2 in N), warp tile 32 x (NTILES*8).
// NTILES=8 -> TBN=128; NTILES=4 -> TBN=64. K1,K2 multiples of 32.
// Software-pipelined: next k-tile's gmem loads issue before the MMA loop.

#define TBM 128
#define TBK 32
#define KSTR 36   // k-minor smem stride; 4*grp+q hits all 32 banks conflict-free

__device__ __forceinline__ uint32_t f2tf32(float f) {
    uint32_t u;
    asm("cvt.rna.tf32.f32 %0, %1;" : "=r"(u) : "f"(f));
    return u;
}

__device__ __forceinline__ void mma_tf32(float c[4],
                                         uint32_t a0, uint32_t a1, uint32_t a2, uint32_t a3,
                                         uint32_t b0, uint32_t b1) {
    asm volatile(
        "mma.sync.aligned.m16n8k8.row.col.f32.tf32.tf32.f32 "
        "{%0,%1,%2,%3}, {%4,%5,%6,%7}, {%8,%9}, {%0,%1,%2,%3};"
        : "+f"(c[0]), "+f"(c[1]), "+f"(c[2]), "+f"(c[3])
        : "r"(a0), "r"(a1), "r"(a2), "r"(a3), "r"(b0), "r"(b1));
}

template <int NTILES>
__global__ __launch_bounds__(256) void gemm_tf32_kernel(
    const float* __restrict__ A1, int lda1, int K1,
    const float* __restrict__ A2, int lda2, int K2,
    const float* __restrict__ B1, const float* __restrict__ B2,
    const float* __restrict__ bias,
    float* __restrict__ C, int ldc,
    int M, int Ncol, int do_relu)
{
    constexpr int TBN = NTILES * 16;          // 128 or 64
    constexpr int B_IT = TBN / 32;            // float4 loads per thread for B tile
    constexpr int NQ4 = TBN / 4;              // float4s per B row

    __shared__ uint32_t As[TBM][KSTR];
    __shared__ uint32_t Bs[TBN][KSTR];

    int tid = threadIdx.x;
    int lane = tid & 31;
    int wid = tid >> 5;
    int grp = lane >> 2;
    int q = lane & 3;
    int warp_m = (wid & 3) * 32;
    int warp_n = (wid >> 2) * (NTILES * 8);
    int rowbase = blockIdx.y * TBM;
    int colbase = blockIdx.x * TBN;

    float acc[2][NTILES][4];
#pragma unroll
    for (int mt = 0; mt < 2; mt++)
#pragma unroll
        for (int nt = 0; nt < NTILES; nt++)
#pragma unroll
            for (int r = 0; r < 4; r++) acc[mt][nt][r] = 0.f;

    int K = K1 + K2;
    float4 ar[4], br[B_IT];

    // prologue: load tile 0
    {
        const float* Ap; const float* Bp; int lda, koff;
        if (0 < K1) { Ap = A1; lda = lda1; Bp = B1; koff = 0; }
        else        { Ap = A2; lda = lda2; Bp = B2; koff = 0; }
#pragma unroll
        for (int it = 0; it < 4; it++) {
            int idx = tid + it * 256;
            int row = idx >> 3, kq = (idx & 7) * 4;
            int r = rowbase + row;
            ar[it] = make_float4(0.f, 0.f, 0.f, 0.f);
            if (r < M) ar[it] = *(const float4*)&Ap[(size_t)r * lda + koff + kq];
        }
#pragma unroll
        for (int it = 0; it < B_IT; it++) {
            int idx = tid + it * 256;
            int krow = idx / NQ4, nq = (idx % NQ4) * 4;
            br[it] = *(const float4*)&Bp[(size_t)(koff + krow) * Ncol + colbase + nq];
        }
    }

    for (int kbase = 0; kbase < K; kbase += TBK) {
        // ---- store current tile regs -> smem (with tf32 convert) ----
#pragma unroll
        for (int it = 0; it < 4; it++) {
            int idx = tid + it * 256;
            int row = idx >> 3, kq = (idx & 7) * 4;
            uint4 u;
            u.x = f2tf32(ar[it].x); u.y = f2tf32(ar[it].y);
            u.z = f2tf32(ar[it].z); u.w = f2tf32(ar[it].w);
            *(uint4*)&As[row][kq] = u;
        }
#pragma unroll
        for (int it = 0; it < B_IT; it++) {
            int idx = tid + it * 256;
            int krow = idx / NQ4, nq = (idx % NQ4) * 4;
            Bs[nq + 0][krow] = f2tf32(br[it].x);
            Bs[nq + 1][krow] = f2tf32(br[it].y);
            Bs[nq + 2][krow] = f2tf32(br[it].z);
            Bs[nq + 3][krow] = f2tf32(br[it].w);
        }
        __syncthreads();

        // ---- prefetch next tile into regs (overlaps MMA below) ----
        int knext = kbase + TBK;
        if (knext < K) {
            const float* Ap; const float* Bp; int lda, koff;
            if (knext < K1) { Ap = A1; lda = lda1; Bp = B1; koff = knext; }
            else            { Ap = A2; lda = lda2; Bp = B2; koff = knext - K1; }
#pragma unroll
            for (int it = 0; it < 4; it++) {
                int idx = tid + it * 256;
                int row = idx >> 3, kq = (idx & 7) * 4;
                int r = rowbase + row;
                ar[it] = make_float4(0.f, 0.f, 0.f, 0.f);
                if (r < M) ar[it] = *(const float4*)&Ap[(size_t)r * lda + koff + kq];
            }
#pragma unroll
            for (int it = 0; it < B_IT; it++) {
                int idx = tid + it * 256;
                int krow = idx / NQ4, nq = (idx % NQ4) * 4;
                br[it] = *(const float4*)&Bp[(size_t)(koff + krow) * Ncol + colbase + nq];
            }
        }

        // ---- MMA over the smem tile ----
#pragma unroll
        for (int kc = 0; kc < TBK; kc += 8) {
            uint32_t a[2][4];
#pragma unroll
            for (int mt = 0; mt < 2; mt++) {
                int r = warp_m + mt * 16 + grp;
                a[mt][0] = As[r][kc + q];
                a[mt][1] = As[r + 8][kc + q];
                a[mt][2] = As[r][kc + q + 4];
                a[mt][3] = As[r + 8][kc + q + 4];
            }
#pragma unroll
            for (int nt = 0; nt < NTILES; nt++) {
                int c = warp_n + nt * 8 + grp;
                uint32_t b0 = Bs[c][kc + q];
                uint32_t b1 = Bs[c][kc + q + 4];
#pragma unroll
                for (int mt = 0; mt < 2; mt++)
                    mma_tf32(acc[mt][nt], a[mt][0], a[mt][1], a[mt][2], a[mt][3], b0, b1);
            }
        }
        __syncthreads();
    }

    // ---- epilogue ----
#pragma unroll
    for (int nt = 0; nt < NTILES; nt++) {
        int ccol = colbase + warp_n + nt * 8 + q * 2;
        float bv0 = bias[ccol];
        float bv1 = bias[ccol + 1];
#pragma unroll
        for (int mt = 0; mt < 2; mt++) {
            int r0 = rowbase + warp_m + mt * 16 + grp;
            int r1 = r0 + 8;
            float v0 = acc[mt][nt][0] + bv0;
            float v1 = acc[mt][nt][1] + bv1;
            float v2 = acc[mt][nt][2] + bv0;
            float v3 = acc[mt][nt][3] + bv1;
            if (do_relu) {
                v0 = fmaxf(v0, 0.f); v1 = fmaxf(v1, 0.f);
                v2 = fmaxf(v2, 0.f); v3 = fmaxf(v3, 0.f);
            }
            if (r0 < M) { float2 o = {v0, v1}; *(float2*)&C[(size_t)r0 * ldc + ccol] = o; }
            if (r1 < M) { float2 o = {v2, v3}; *(float2*)&C[(size_t)r1 * ldc + ccol] = o; }
        }
    }
}

// -------------------- launch --------------------
extern "C" void kernel_launch(void* const* d_in, const int* in_sizes, int n_in,
                              void* d_out, int out_size) {
    const float* x   = (const float*)d_in[0];
    const void*  ei  = d_in[1];
    const float* Wl0 = (const float*)d_in[2];
    const float* Wr0 = (const float*)d_in[3];
    const float* b0  = (const float*)d_in[4];
    const float* Wl1 = (const float*)d_in[5];
    const float* Wr1 = (const float*)d_in[6];
    const float* b1  = (const float*)d_in[7];
    const float* Wf  = (const float*)d_in[8];
    const float* bf  = (const float*)d_in[9];
    (void)n_in; (void)out_size;

    int Nn = in_sizes[0] / 128;   // 100000
    int Ee = in_sizes[1] / 2;     // 3200000

    float* out = (float*)d_out;                 // [N, 64]
    float* emb = out + (size_t)Nn * 64;         // [N, 256]

    void *p_agg, *p_h;
    cudaGetSymbolAddress(&p_agg, g_agg);
    cudaGetSymbolAddress(&p_h, g_h);
    float* agg = (float*)p_agg;
    float* h   = (float*)p_h;

    // 0) dtype detect
    detect_kernel<<<1, 64>>>(ei, Nn);

    // 1) CSR build (by dst)
    zero_count_kernel<<<(Nn + 256) / 256, 256>>>(Nn);
    hist_kernel<<<(Ee + 255) / 256, 256>>>(ei, Ee);
    scan_p1<<<SCAN_BLOCKS, SCAN_THREADS>>>(Nn);
    scan_p2<<<1, SCAN_BLOCKS>>>(Ee, Nn);
    scan_p3<<<SCAN_BLOCKS, SCAN_THREADS>>>(Nn);
    scatter_kernel<<<(Ee + 255) / 256, 256>>>(ei, Ee);

    // 2) layer 0: h = relu(x@Wl0 + agg@Wr0 + b0)
    agg_kernel<1><<<(Nn + 7) / 8, 256>>>((const float4*)x, (float4*)agg, Nn);
    {
        dim3 grid(256 / 128, (Nn + TBM - 1) / TBM);
        gemm_tf32_kernel<8><<<grid, 256>>>(x, 128, 128, agg, 128, 128,
                                           Wl0, Wr0, b0, h, 256, Nn, 256, 1);
    }

    // 3) layer 1: emb = relu(h@Wl1 + agg@Wr1 + b1)
    agg_kernel<2><<<(Nn + 7) / 8, 256>>>((const float4*)h, (float4*)agg, Nn);
    {
        dim3 grid(256 / 128, (Nn + TBM - 1) / TBM);
        gemm_tf32_kernel<8><<<grid, 256>>>(h, 256, 256, agg, 256, 256,
                                           Wl1, Wr1, b1, emb, 256, Nn, 256, 1);
    }

    // 4) head: out = emb @ Wf + bf   (tf32, TBN=64)
    {
        dim3 grid(1, (Nn + TBM - 1) / TBM);
        gemm_tf32_kernel<4><<<grid, 256>>>(emb, 256, 256, emb, 256, 0,
                                           Wf, Wf, bf, out, 64, Nn, 64, 0);
    }
}

// round 7
// speedup vs baseline: 1.8760x; 1.0326x over previous
#include <cuda_runtime.h>
#include <cuda_bf16.h>
#include <cstdint>

#define N_MAX 100000
#define E_MAX 3200000
#define SCAN_BLOCKS 128
#define SCAN_THREADS 256

// -------------------- device scratch --------------------
__device__ float g_agg[(size_t)N_MAX * 256];
__device__ float g_h[(size_t)N_MAX * 256];
__device__ float g_tmp[(size_t)N_MAX * 256];
__device__ __nv_bfloat16 g_hbf[(size_t)N_MAX * 256];
__device__ int   g_count[N_MAX + 1];
__device__ int   g_rowptr[N_MAX + 1];
__device__ int   g_cursor[N_MAX];
__device__ float g_invdeg[N_MAX];
__device__ int   g_srcs[E_MAX];
__device__ int   g_is64;
__device__ int   g_bsum[SCAN_BLOCKS];
__device__ int   g_boff[SCAN_BLOCKS];

// -------------------- dtype detection --------------------
__global__ void detect_kernel(const void* ei, int Nn) {
    const long long* p = (const long long*)ei;
    int t = threadIdx.x;
    long long v = p[t];
    int bad = (v < 0 || v >= (long long)Nn);
    unsigned m = __ballot_sync(0xFFFFFFFFu, bad);
    __shared__ unsigned sm[2];
    if ((t & 31) == 0) sm[t >> 5] = m;
    __syncthreads();
    if (t == 0) g_is64 = (sm[0] | sm[1]) == 0u;
}

__device__ __forceinline__ int load_idx(const void* ei, long long pos) {
    if (g_is64) return (int)((const long long*)ei)[pos];
    return ((const int*)ei)[pos];
}

// -------------------- CSR build --------------------
__global__ void zero_count_kernel(int n) {
    int i = blockIdx.x * blockDim.x + threadIdx.x;
    if (i <= n) g_count[i] = 0;
}

__global__ void hist_kernel(const void* __restrict__ ei, int E) {
    int e = blockIdx.x * blockDim.x + threadIdx.x;
    if (e < E) atomicAdd(&g_count[load_idx(ei, (long long)E + e)], 1);
}

__device__ __forceinline__ void chunk_bounds(int Nn, int b, int t, int& tb, int& te) {
    int chunk = (Nn + SCAN_BLOCKS - 1) / SCAN_BLOCKS;
    int bbeg = b * chunk;
    int bend = min(bbeg + chunk, Nn);
    int tCH = (chunk + SCAN_THREADS - 1) / SCAN_THREADS;
    tb = bbeg + t * tCH;
    te = min(tb + tCH, bend);
}

__global__ void scan_p1(int Nn) {
    __shared__ int sh[SCAN_THREADS];
    int b = blockIdx.x, t = threadIdx.x;
    int tb, te; chunk_bounds(Nn, b, t, tb, te);
    int s = 0;
    for (int i = tb; i < te; i++) s += g_count[i];
    sh[t] = s;
    __syncthreads();
    for (int off = SCAN_THREADS / 2; off > 0; off >>= 1) {
        if (t < off) sh[t] += sh[t + off];
        __syncthreads();
    }
    if (t == 0) g_bsum[b] = sh[0];
}

__global__ void scan_p2(int Ee, int Nn) {
    __shared__ int sh[SCAN_BLOCKS];
    int t = threadIdx.x;
    int v = (t < SCAN_BLOCKS) ? g_bsum[t] : 0;
    if (t < SCAN_BLOCKS) sh[t] = v;
    __syncthreads();
    for (int off = 1; off < SCAN_BLOCKS; off <<= 1) {
        int u = 0;
        if (t < SCAN_BLOCKS && t >= off) u = sh[t - off];
        __syncthreads();
        if (t < SCAN_BLOCKS && t >= off) sh[t] += u;
        __syncthreads();
    }
    if (t < SCAN_BLOCKS) g_boff[t] = sh[t] - v;
    if (t == 0) g_rowptr[Nn] = Ee;
}

__global__ void scan_p3(int Nn) {
    __shared__ int sh[SCAN_THREADS];
    int b = blockIdx.x, t = threadIdx.x;
    int tb, te; chunk_bounds(Nn, b, t, tb, te);
    int s = 0;
    for (int i = tb; i < te; i++) s += g_count[i];
    sh[t] = s;
    __syncthreads();
    for (int off = 1; off < SCAN_THREADS; off <<= 1) {
        int u = 0;
        if (t >= off) u = sh[t - off];
        __syncthreads();
        if (t >= off) sh[t] += u;
        __syncthreads();
    }
    int run = sh[t] - s + g_boff[b];
    for (int i = tb; i < te; i++) {
        int c = g_count[i];
        g_rowptr[i] = run;
        g_cursor[i] = run;
        g_invdeg[i] = 1.0f / (float)max(c, 1);
        run += c;
    }
}

__global__ void scatter_kernel(const void* __restrict__ ei, int E) {
    int e = blockIdx.x * blockDim.x + threadIdx.x;
    if (e < E) {
        int s = load_idx(ei, e);
        int d = load_idx(ei, (long long)E + e);
        int pos = atomicAdd(&g_cursor[d], 1);
        g_srcs[pos] = s;
    }
}

// -------------------- mean aggregation (fp32 gather, 128 features) ----------
__global__ void agg_f32_kernel(const float4* __restrict__ X, float4* __restrict__ out, int Nn) {
    int w = (blockIdx.x * blockDim.x + threadIdx.x) >> 5;
    int lane = threadIdx.x & 31;
    if (w >= Nn) return;
    int beg = g_rowptr[w];
    int end = g_rowptr[w + 1];
    float4 acc = make_float4(0.f, 0.f, 0.f, 0.f);
    for (int e = beg; e < end; e++) {
        int s = g_srcs[e];
        float4 v = __ldg(&X[(size_t)s * 32 + lane]);
        acc.x += v.x; acc.y += v.y; acc.z += v.z; acc.w += v.w;
    }
    float inv = g_invdeg[w];
    float4 r;
    r.x = acc.x * inv; r.y = acc.y * inv; r.z = acc.z * inv; r.w = acc.w * inv;
    out[(size_t)w * 32 + lane] = r;
}

// -------------------- mean aggregation (bf16 gather, 256 features) ----------
__global__ void agg_bf16_kernel(const __nv_bfloat16* __restrict__ Xb,
                                float4* __restrict__ out, int Nn) {
    int w = (blockIdx.x * blockDim.x + threadIdx.x) >> 5;
    int lane = threadIdx.x & 31;
    if (w >= Nn) return;
    int beg = g_rowptr[w];
    int end = g_rowptr[w + 1];
    float acc[8];
#pragma unroll
    for (int i = 0; i < 8; i++) acc[i] = 0.f;
    for (int e = beg; e < end; e++) {
        int s = g_srcs[e];
        const uint4* row = (const uint4*)(Xb + (size_t)s * 256);
        uint4 v = __ldg(&row[lane]);
        float2 f0 = __bfloat1622float2(*(__nv_bfloat162*)&v.x);
        float2 f1 = __bfloat1622float2(*(__nv_bfloat162*)&v.y);
        float2 f2 = __bfloat1622float2(*(__nv_bfloat162*)&v.z);
        float2 f3 = __bfloat1622float2(*(__nv_bfloat162*)&v.w);
        acc[0] += f0.x; acc[1] += f0.y;
        acc[2] += f1.x; acc[3] += f1.y;
        acc[4] += f2.x; acc[5] += f2.y;
        acc[6] += f3.x; acc[7] += f3.y;
    }
    float inv = g_invdeg[w];
    float4 r0, r1;
    r0.x = acc[0] * inv; r0.y = acc[1] * inv; r0.z = acc[2] * inv; r0.w = acc[3] * inv;
    r1.x = acc[4] * inv; r1.y = acc[5] * inv; r1.z = acc[6] * inv; r1.w = acc[7] * inv;
    out[(size_t)w * 64 + lane * 2]     = r0;
    out[(size_t)w * 64 + lane * 2 + 1] = r1;
}

// -------------------- TF32 tensor-core GEMM (mma.sync m16n8k8) --------------------
// C = act( A @ B + bias? + Cin? ), optional bf16 mirror of C.
// Block tile 128 x TBN x 32, 8 warps, pipelined gmem->reg prefetch.

#define TBM 128
#define TBK 32
#define KSTR 36

__device__ __forceinline__ uint32_t f2tf32(float f) {
    uint32_t u;
    asm("cvt.rna.tf32.f32 %0, %1;" : "=r"(u) : "f"(f));
    return u;
}

__device__ __forceinline__ void mma_tf32(float c[4],
                                         uint32_t a0, uint32_t a1, uint32_t a2, uint32_t a3,
                                         uint32_t b0, uint32_t b1) {
    asm volatile(
        "mma.sync.aligned.m16n8k8.row.col.f32.tf32.tf32.f32 "
        "{%0,%1,%2,%3}, {%4,%5,%6,%7}, {%8,%9}, {%0,%1,%2,%3};"
        : "+f"(c[0]), "+f"(c[1]), "+f"(c[2]), "+f"(c[3])
        : "r"(a0), "r"(a1), "r"(a2), "r"(a3), "r"(b0), "r"(b1));
}

template <int NTILES>
__global__ __launch_bounds__(256) void gemm_tf32_kernel(
    const float* __restrict__ A, int lda, int K,
    const float* __restrict__ B,              // [K, Ncol] row-major
    const float* __restrict__ bias,           // nullable
    const float* __restrict__ Cin,            // nullable, same ldc as C
    float* __restrict__ C, int ldc,
    __nv_bfloat16* __restrict__ Cbf,          // nullable, same ldc
    int M, int Ncol, int do_relu)
{
    constexpr int TBN = NTILES * 16;
    constexpr int B_IT = TBN / 32;
    constexpr int NQ4 = TBN / 4;

    __shared__ uint32_t As[TBM][KSTR];
    __shared__ uint32_t Bs[TBN][KSTR];

    int tid = threadIdx.x;
    int lane = tid & 31;
    int wid = tid >> 5;
    int grp = lane >> 2;
    int q = lane & 3;
    int warp_m = (wid & 3) * 32;
    int warp_n = (wid >> 2) * (NTILES * 8);
    int rowbase = blockIdx.y * TBM;
    int colbase = blockIdx.x * TBN;

    float acc[2][NTILES][4];
#pragma unroll
    for (int mt = 0; mt < 2; mt++)
#pragma unroll
        for (int nt = 0; nt < NTILES; nt++)
#pragma unroll
            for (int r = 0; r < 4; r++) acc[mt][nt][r] = 0.f;

    float4 ar[4], br[B_IT];

    // prologue: load tile 0 into regs
#pragma unroll
    for (int it = 0; it < 4; it++) {
        int idx = tid + it * 256;
        int row = idx >> 3, kq = (idx & 7) * 4;
        int r = rowbase + row;
        ar[it] = make_float4(0.f, 0.f, 0.f, 0.f);
        if (r < M) ar[it] = *(const float4*)&A[(size_t)r * lda + kq];
    }
#pragma unroll
    for (int it = 0; it < B_IT; it++) {
        int idx = tid + it * 256;
        int krow = idx / NQ4, nq = (idx % NQ4) * 4;
        br[it] = *(const float4*)&B[(size_t)krow * Ncol + colbase + nq];
    }

    for (int kbase = 0; kbase < K; kbase += TBK) {
        // regs -> smem (tf32 convert)
#pragma unroll
        for (int it = 0; it < 4; it++) {
            int idx = tid + it * 256;
            int row = idx >> 3, kq = (idx & 7) * 4;
            uint4 u;
            u.x = f2tf32(ar[it].x); u.y = f2tf32(ar[it].y);
            u.z = f2tf32(ar[it].z); u.w = f2tf32(ar[it].w);
            *(uint4*)&As[row][kq] = u;
        }
#pragma unroll
        for (int it = 0; it < B_IT; it++) {
            int idx = tid + it * 256;
            int krow = idx / NQ4, nq = (idx % NQ4) * 4;
            Bs[nq + 0][krow] = f2tf32(br[it].x);
            Bs[nq + 1][krow] = f2tf32(br[it].y);
            Bs[nq + 2][krow] = f2tf32(br[it].z);
            Bs[nq + 3][krow] = f2tf32(br[it].w);
        }
        __syncthreads();

        // prefetch next k-tile
        int knext = kbase + TBK;
        if (knext < K) {
#pragma unroll
            for (int it = 0; it < 4; it++) {
                int idx = tid + it * 256;
                int row = idx >> 3, kq = (idx & 7) * 4;
                int r = rowbase + row;
                ar[it] = make_float4(0.f, 0.f, 0.f, 0.f);
                if (r < M) ar[it] = *(const float4*)&A[(size_t)r * lda + knext + kq];
            }
#pragma unroll
            for (int it = 0; it < B_IT; it++) {
                int idx = tid + it * 256;
                int krow = idx / NQ4, nq = (idx % NQ4) * 4;
                br[it] = *(const float4*)&B[(size_t)(knext + krow) * Ncol + colbase + nq];
            }
        }

        // MMA over smem tile
#pragma unroll
        for (int kc = 0; kc < TBK; kc += 8) {
            uint32_t a[2][4];
#pragma unroll
            for (int mt = 0; mt < 2; mt++) {
                int r = warp_m + mt * 16 + grp;
                a[mt][0] = As[r][kc + q];
                a[mt][1] = As[r + 8][kc + q];
                a[mt][2] = As[r][kc + q + 4];
                a[mt][3] = As[r + 8][kc + q + 4];
            }
#pragma unroll
            for (int nt = 0; nt < NTILES; nt++) {
                int c = warp_n + nt * 8 + grp;
                uint32_t b0 = Bs[c][kc + q];
                uint32_t b1 = Bs[c][kc + q + 4];
#pragma unroll
                for (int mt = 0; mt < 2; mt++)
                    mma_tf32(acc[mt][nt], a[mt][0], a[mt][1], a[mt][2], a[mt][3], b0, b1);
            }
        }
        __syncthreads();
    }

    // ---- epilogue ----
#pragma unroll
    for (int nt = 0; nt < NTILES; nt++) {
        int ccol = colbase + warp_n + nt * 8 + q * 2;
        float bv0 = 0.f, bv1 = 0.f;
        if (bias) { bv0 = bias[ccol]; bv1 = bias[ccol + 1]; }
#pragma unroll
        for (int mt = 0; mt < 2; mt++) {
            int r0 = rowbase + warp_m + mt * 16 + grp;
            int r1 = r0 + 8;
            float v0 = acc[mt][nt][0] + bv0;
            float v1 = acc[mt][nt][1] + bv1;
            float v2 = acc[mt][nt][2] + bv0;
            float v3 = acc[mt][nt][3] + bv1;
            if (Cin) {
                if (r0 < M) { float2 ci = *(const float2*)&Cin[(size_t)r0 * ldc + ccol]; v0 += ci.x; v1 += ci.y; }
                if (r1 < M) { float2 ci = *(const float2*)&Cin[(size_t)r1 * ldc + ccol]; v2 += ci.x; v3 += ci.y; }
            }
            if (do_relu) {
                v0 = fmaxf(v0, 0.f); v1 = fmaxf(v1, 0.f);
                v2 = fmaxf(v2, 0.f); v3 = fmaxf(v3, 0.f);
            }
            if (r0 < M) {
                float2 o = {v0, v1};
                *(float2*)&C[(size_t)r0 * ldc + ccol] = o;
                if (Cbf) *(__nv_bfloat162*)&Cbf[(size_t)r0 * ldc + ccol] = __floats2bfloat162_rn(v0, v1);
            }
            if (r1 < M) {
                float2 o = {v2, v3};
                *(float2*)&C[(size_t)r1 * ldc + ccol] = o;
                if (Cbf) *(__nv_bfloat162*)&Cbf[(size_t)r1 * ldc + ccol] = __floats2bfloat162_rn(v2, v3);
            }
        }
    }
}

// -------------------- launch --------------------
extern "C" void kernel_launch(void* const* d_in, const int* in_sizes, int n_in,
                              void* d_out, int out_size) {
    const float* x   = (const float*)d_in[0];
    const void*  ei  = d_in[1];
    const float* Wl0 = (const float*)d_in[2];
    const float* Wr0 = (const float*)d_in[3];
    const float* b0  = (const float*)d_in[4];
    const float* Wl1 = (const float*)d_in[5];
    const float* Wr1 = (const float*)d_in[6];
    const float* b1  = (const float*)d_in[7];
    const float* Wf  = (const float*)d_in[8];
    const float* bf  = (const float*)d_in[9];
    (void)n_in; (void)out_size;

    int Nn = in_sizes[0] / 128;   // 100000
    int Ee = in_sizes[1] / 2;     // 3200000

    float* out = (float*)d_out;                 // [N, 64]
    float* emb = out + (size_t)Nn * 64;         // [N, 256]

    void *p_agg, *p_h, *p_tmp, *p_hbf;
    cudaGetSymbolAddress(&p_agg, g_agg);
    cudaGetSymbolAddress(&p_h, g_h);
    cudaGetSymbolAddress(&p_tmp, g_tmp);
    cudaGetSymbolAddress(&p_hbf, g_hbf);
    float* agg = (float*)p_agg;
    float* h   = (float*)p_h;
    float* tmp = (float*)p_tmp;
    __nv_bfloat16* hbf = (__nv_bfloat16*)p_hbf;

    dim3 gemm_grid(2, (Nn + TBM - 1) / TBM);        // TBN=128, Ncol=256
    dim3 head_grid(1, (Nn + TBM - 1) / TBM);        // TBN=64,  Ncol=64

    // side stream + events for capture-legal fork/join (host objects; leaked —
    // kernel_launch is only invoked a handful of times, replays use the graph)
    cudaStream_t s2;
    cudaStreamCreateWithFlags(&s2, cudaStreamNonBlocking);
    cudaEvent_t evF1, evJ1, evF2, evJ2;
    cudaEventCreateWithFlags(&evF1, cudaEventDisableTiming);
    cudaEventCreateWithFlags(&evJ1, cudaEventDisableTiming);
    cudaEventCreateWithFlags(&evF2, cudaEventDisableTiming);
    cudaEventCreateWithFlags(&evJ2, cudaEventDisableTiming);

    // 0) dtype detect (main stream)
    detect_kernel<<<1, 64>>>(ei, Nn);

    // ---- fork 1: t0 = x@Wl0 + b0 on s2, CSR + agg0 on main ----
    cudaEventRecord(evF1, 0);
    cudaStreamWaitEvent(s2, evF1, 0);

    gemm_tf32_kernel<8><<<gemm_grid, 256, 0, s2>>>(
        x, 128, 128, Wl0, b0, nullptr, tmp, 256, nullptr, Nn, 256, 0);

    zero_count_kernel<<<(Nn + 256) / 256, 256>>>(Nn);
    hist_kernel<<<(Ee + 255) / 256, 256>>>(ei, Ee);
    scan_p1<<<SCAN_BLOCKS, SCAN_THREADS>>>(Nn);
    scan_p2<<<1, SCAN_BLOCKS>>>(Ee, Nn);
    scan_p3<<<SCAN_BLOCKS, SCAN_THREADS>>>(Nn);
    scatter_kernel<<<(Ee + 255) / 256, 256>>>(ei, Ee);
    agg_f32_kernel<<<(Nn + 7) / 8, 256>>>((const float4*)x, (float4*)agg, Nn);

    cudaEventRecord(evJ1, s2);
    cudaStreamWaitEvent(0, evJ1, 0);

    // join: h = relu(tmp + agg0@Wr0), also emit bf16 h
    gemm_tf32_kernel<8><<<gemm_grid, 256>>>(
        agg, 128, 128, Wr0, nullptr, tmp, h, 256, hbf, Nn, 256, 1);

    // ---- fork 2: t1 = h@Wl1 + b1 on s2, agg1 (bf16 gather) on main ----
    cudaEventRecord(evF2, 0);
    cudaStreamWaitEvent(s2, evF2, 0);

    gemm_tf32_kernel<8><<<gemm_grid, 256, 0, s2>>>(
        h, 256, 256, Wl1, b1, nullptr, tmp, 256, nullptr, Nn, 256, 0);

    agg_bf16_kernel<<<(Nn + 7) / 8, 256>>>(hbf, (float4*)agg, Nn);

    cudaEventRecord(evJ2, s2);
    cudaStreamWaitEvent(0, evJ2, 0);

    // join: emb = relu(tmp + agg1@Wr1)
    gemm_tf32_kernel<8><<<gemm_grid, 256>>>(
        agg, 256, 256, Wr1, nullptr, tmp, emb, 256, nullptr, Nn, 256, 1);

    // head: out = emb @ Wf + bf
    gemm_tf32_kernel<4><<<head_grid, 256>>>(
        emb, 256, 256, Wf, bf, nullptr, out, 64, nullptr, Nn, 64, 0);
}

// round 9
// speedup vs baseline: 1.9556x; 1.0424x over previous
#include <cuda_runtime.h>
#include <cuda_bf16.h>
#include <cstdint>

#define N_MAX 100000
#define E_MAX 3200000
#define SCAN_BLOCKS 128
#define SCAN_THREADS 256

// -------------------- device scratch --------------------
__device__ float g_agg[(size_t)N_MAX * 256];
__device__ float g_h[(size_t)N_MAX * 256];
__device__ float g_tmp[(size_t)N_MAX * 256];
__device__ __nv_bfloat16 g_hbf[(size_t)N_MAX * 256];
__device__ int   g_count[N_MAX + 1];
__device__ int   g_rowptr[N_MAX + 1];
__device__ int   g_cursor[N_MAX];
__device__ float g_invdeg[N_MAX];
__device__ int   g_srcs[E_MAX];
__device__ int   g_is64;
__device__ int   g_bsum[SCAN_BLOCKS];
__device__ int   g_boff[SCAN_BLOCKS];

// -------------------- dtype detection --------------------
__global__ void detect_kernel(const void* ei, int Nn) {
    const long long* p = (const long long*)ei;
    int t = threadIdx.x;
    long long v = p[t];
    int bad = (v < 0 || v >= (long long)Nn);
    unsigned m = __ballot_sync(0xFFFFFFFFu, bad);
    __shared__ unsigned sm[2];
    if ((t & 31) == 0) sm[t >> 5] = m;
    __syncthreads();
    if (t == 0) g_is64 = (sm[0] | sm[1]) == 0u;
}

__device__ __forceinline__ int load_idx(const void* ei, long long pos) {
    if (g_is64) return (int)((const long long*)ei)[pos];
    return ((const int*)ei)[pos];
}

// -------------------- CSR build --------------------
__global__ void zero_count_kernel(int n) {
    int i = blockIdx.x * blockDim.x + threadIdx.x;
    if (i <= n) g_count[i] = 0;
}

__global__ void hist_kernel(const void* __restrict__ ei, int E) {
    int e = blockIdx.x * blockDim.x + threadIdx.x;
    if (e < E) atomicAdd(&g_count[load_idx(ei, (long long)E + e)], 1);
}

__device__ __forceinline__ void chunk_bounds(int Nn, int b, int t, int& tb, int& te) {
    int chunk = (Nn + SCAN_BLOCKS - 1) / SCAN_BLOCKS;
    int bbeg = b * chunk;
    int bend = min(bbeg + chunk, Nn);
    int tCH = (chunk + SCAN_THREADS - 1) / SCAN_THREADS;
    tb = bbeg + t * tCH;
    te = min(tb + tCH, bend);
}

__global__ void scan_p1(int Nn) {
    __shared__ int sh[SCAN_THREADS];
    int b = blockIdx.x, t = threadIdx.x;
    int tb, te; chunk_bounds(Nn, b, t, tb, te);
    int s = 0;
    for (int i = tb; i < te; i++) s += g_count[i];
    sh[t] = s;
    __syncthreads();
    for (int off = SCAN_THREADS / 2; off > 0; off >>= 1) {
        if (t < off) sh[t] += sh[t + off];
        __syncthreads();
    }
    if (t == 0) g_bsum[b] = sh[0];
}

__global__ void scan_p2(int Ee, int Nn) {
    __shared__ int sh[SCAN_BLOCKS];
    int t = threadIdx.x;
    int v = (t < SCAN_BLOCKS) ? g_bsum[t] : 0;
    if (t < SCAN_BLOCKS) sh[t] = v;
    __syncthreads();
    for (int off = 1; off < SCAN_BLOCKS; off <<= 1) {
        int u = 0;
        if (t < SCAN_BLOCKS && t >= off) u = sh[t - off];
        __syncthreads();
        if (t < SCAN_BLOCKS && t >= off) sh[t] += u;
        __syncthreads();
    }
    if (t < SCAN_BLOCKS) g_boff[t] = sh[t] - v;
    if (t == 0) g_rowptr[Nn] = Ee;
}

__global__ void scan_p3(int Nn) {
    __shared__ int sh[SCAN_THREADS];
    int b = blockIdx.x, t = threadIdx.x;
    int tb, te; chunk_bounds(Nn, b, t, tb, te);
    int s = 0;
    for (int i = tb; i < te; i++) s += g_count[i];
    sh[t] = s;
    __syncthreads();
    for (int off = 1; off < SCAN_THREADS; off <<= 1) {
        int u = 0;
        if (t >= off) u = sh[t - off];
        __syncthreads();
        if (t >= off) sh[t] += u;
        __syncthreads();
    }
    int run = sh[t] - s + g_boff[b];
    for (int i = tb; i < te; i++) {
        int c = g_count[i];
        g_rowptr[i] = run;
        g_cursor[i] = run;
        g_invdeg[i] = 1.0f / (float)max(c, 1);
        run += c;
    }
}

__global__ void scatter_kernel(const void* __restrict__ ei, int E) {
    int e = blockIdx.x * blockDim.x + threadIdx.x;
    if (e < E) {
        int s = load_idx(ei, e);
        int d = load_idx(ei, (long long)E + e);
        int pos = atomicAdd(&g_cursor[d], 1);
        g_srcs[pos] = s;
    }
}

// -------------------- mean aggregation (fp32 gather, 128 features) ----------
__global__ void agg_f32_kernel(const float4* __restrict__ X, float4* __restrict__ out, int Nn) {
    int w = (blockIdx.x * blockDim.x + threadIdx.x) >> 5;
    int lane = threadIdx.x & 31;
    if (w >= Nn) return;
    int beg = g_rowptr[w];
    int end = g_rowptr[w + 1];
    float4 acc = make_float4(0.f, 0.f, 0.f, 0.f);
    for (int e = beg; e < end; e++) {
        int s = g_srcs[e];
        float4 v = __ldg(&X[(size_t)s * 32 + lane]);
        acc.x += v.x; acc.y += v.y; acc.z += v.z; acc.w += v.w;
    }
    float inv = g_invdeg[w];
    float4 r;
    r.x = acc.x * inv; r.y = acc.y * inv; r.z = acc.z * inv; r.w = acc.w * inv;
    out[(size_t)w * 32 + lane] = r;
}

// -------------------- mean aggregation (bf16 gather, 256 features) ----------
__global__ void agg_bf16_kernel(const __nv_bfloat16* __restrict__ Xb,
                                float4* __restrict__ out, int Nn) {
    int w = (blockIdx.x * blockDim.x + threadIdx.x) >> 5;
    int lane = threadIdx.x & 31;
    if (w >= Nn) return;
    int beg = g_rowptr[w];
    int end = g_rowptr[w + 1];
    float acc[8];
#pragma unroll
    for (int i = 0; i < 8; i++) acc[i] = 0.f;
    for (int e = beg; e < end; e++) {
        int s = g_srcs[e];
        const uint4* row = (const uint4*)(Xb + (size_t)s * 256);
        uint4 v = __ldg(&row[lane]);
        float2 f0 = __bfloat1622float2(*(__nv_bfloat162*)&v.x);
        float2 f1 = __bfloat1622float2(*(__nv_bfloat162*)&v.y);
        float2 f2 = __bfloat1622float2(*(__nv_bfloat162*)&v.z);
        float2 f3 = __bfloat1622float2(*(__nv_bfloat162*)&v.w);
        acc[0] += f0.x; acc[1] += f0.y;
        acc[2] += f1.x; acc[3] += f1.y;
        acc[4] += f2.x; acc[5] += f2.y;
        acc[6] += f3.x; acc[7] += f3.y;
    }
    float inv = g_invdeg[w];
    float4 r0, r1;
    r0.x = acc[0] * inv; r0.y = acc[1] * inv; r0.z = acc[2] * inv; r0.w = acc[3] * inv;
    r1.x = acc[4] * inv; r1.y = acc[5] * inv; r1.z = acc[6] * inv; r1.w = acc[7] * inv;
    out[(size_t)w * 64 + lane * 2]     = r0;
    out[(size_t)w * 64 + lane * 2 + 1] = r1;
}

// -------------------- TF32 tensor-core GEMM (mma.sync m16n8k8) --------------------
// C = act( A1@B1 [+ A2@B2] + bias? + Cin? ), optional bf16 mirror.
// Block tile 128 x (NTILES*16) x 32, 8 warps, pipelined gmem->reg prefetch.

#define TBM 128
#define TBK 32
#define KSTR 36

__device__ __forceinline__ uint32_t f2tf32(float f) {
    uint32_t u;
    asm("cvt.rna.tf32.f32 %0, %1;" : "=r"(u) : "f"(f));
    return u;
}

__device__ __forceinline__ void mma_tf32(float c[4],
                                         uint32_t a0, uint32_t a1, uint32_t a2, uint32_t a3,
                                         uint32_t b0, uint32_t b1) {
    asm volatile(
        "mma.sync.aligned.m16n8k8.row.col.f32.tf32.tf32.f32 "
        "{%0,%1,%2,%3}, {%4,%5,%6,%7}, {%8,%9}, {%0,%1,%2,%3};"
        : "+f"(c[0]), "+f"(c[1]), "+f"(c[2]), "+f"(c[3])
        : "r"(a0), "r"(a1), "r"(a2), "r"(a3), "r"(b0), "r"(b1));
}

template <int NTILES>
__global__ __launch_bounds__(256) void gemm_tf32_kernel(
    const float* __restrict__ A1, int lda1, int K1,
    const float* __restrict__ A2, int lda2, int K2,   // A2 nullable (K2=0)
    const float* __restrict__ B1, const float* __restrict__ B2,
    const float* __restrict__ bias,                   // nullable
    const float* __restrict__ Cin,                    // nullable
    float* __restrict__ C, int ldc,
    __nv_bfloat16* __restrict__ Cbf,                  // nullable
    int M, int Ncol, int do_relu)
{
    constexpr int TBN = NTILES * 16;
    constexpr int B_IT = TBN / 32;
    constexpr int NQ4 = TBN / 4;

    __shared__ uint32_t As[TBM][KSTR];
    __shared__ uint32_t Bs[TBN][KSTR];

    int tid = threadIdx.x;
    int lane = tid & 31;
    int wid = tid >> 5;
    int grp = lane >> 2;
    int q = lane & 3;
    int warp_m = (wid & 3) * 32;
    int warp_n = (wid >> 2) * (NTILES * 8);
    int rowbase = blockIdx.y * TBM;
    int colbase = blockIdx.x * TBN;

    float acc[2][NTILES][4];
#pragma unroll
    for (int mt = 0; mt < 2; mt++)
#pragma unroll
        for (int nt = 0; nt < NTILES; nt++)
#pragma unroll
            for (int r = 0; r < 4; r++) acc[mt][nt][r] = 0.f;

    int K = K1 + K2;
    float4 ar[4], br[B_IT];

    // prologue: load tile 0 into regs
    {
        const float* Ap = A1; const float* Bp = B1; int lda = lda1, koff = 0;
#pragma unroll
        for (int it = 0; it < 4; it++) {
            int idx = tid + it * 256;
            int row = idx >> 3, kq = (idx & 7) * 4;
            int r = rowbase + row;
            ar[it] = make_float4(0.f, 0.f, 0.f, 0.f);
            if (r < M) ar[it] = *(const float4*)&Ap[(size_t)r * lda + koff + kq];
        }
#pragma unroll
        for (int it = 0; it < B_IT; it++) {
            int idx = tid + it * 256;
            int krow = idx / NQ4, nq = (idx % NQ4) * 4;
            br[it] = *(const float4*)&Bp[(size_t)(koff + krow) * Ncol + colbase + nq];
        }
    }

    for (int kbase = 0; kbase < K; kbase += TBK) {
        // regs -> smem (tf32 convert)
#pragma unroll
        for (int it = 0; it < 4; it++) {
            int idx = tid + it * 256;
            int row = idx >> 3, kq = (idx & 7) * 4;
            uint4 u;
            u.x = f2tf32(ar[it].x); u.y = f2tf32(ar[it].y);
            u.z = f2tf32(ar[it].z); u.w = f2tf32(ar[it].w);
            *(uint4*)&As[row][kq] = u;
        }
#pragma unroll
        for (int it = 0; it < B_IT; it++) {
            int idx = tid + it * 256;
            int krow = idx / NQ4, nq = (idx % NQ4) * 4;
            Bs[nq + 0][krow] = f2tf32(br[it].x);
            Bs[nq + 1][krow] = f2tf32(br[it].y);
            Bs[nq + 2][krow] = f2tf32(br[it].z);
            Bs[nq + 3][krow] = f2tf32(br[it].w);
        }
        __syncthreads();

        // prefetch next k-tile (overlaps MMA)
        int knext = kbase + TBK;
        if (knext < K) {
            const float* Ap; const float* Bp; int lda, koff;
            if (knext < K1) { Ap = A1; lda = lda1; Bp = B1; koff = knext; }
            else            { Ap = A2; lda = lda2; Bp = B2; koff = knext - K1; }
#pragma unroll
            for (int it = 0; it < 4; it++) {
                int idx = tid + it * 256;
                int row = idx >> 3, kq = (idx & 7) * 4;
                int r = rowbase + row;
                ar[it] = make_float4(0.f, 0.f, 0.f, 0.f);
                if (r < M) ar[it] = *(const float4*)&Ap[(size_t)r * lda + koff + kq];
            }
#pragma unroll
            for (int it = 0; it < B_IT; it++) {
                int idx = tid + it * 256;
                int krow = idx / NQ4, nq = (idx % NQ4) * 4;
                br[it] = *(const float4*)&Bp[(size_t)(koff + krow) * Ncol + colbase + nq];
            }
        }

        // MMA over smem tile
#pragma unroll
        for (int kc = 0; kc < TBK; kc += 8) {
            uint32_t a[2][4];
#pragma unroll
            for (int mt = 0; mt < 2; mt++) {
                int r = warp_m + mt * 16 + grp;
                a[mt][0] = As[r][kc + q];
                a[mt][1] = As[r + 8][kc + q];
                a[mt][2] = As[r][kc + q + 4];
                a[mt][3] = As[r + 8][kc + q + 4];
            }
#pragma unroll
            for (int nt = 0; nt < NTILES; nt++) {
                int c = warp_n + nt * 8 + grp;
                uint32_t b0 = Bs[c][kc + q];
                uint32_t b1 = Bs[c][kc + q + 4];
#pragma unroll
                for (int mt = 0; mt < 2; mt++)
                    mma_tf32(acc[mt][nt], a[mt][0], a[mt][1], a[mt][2], a[mt][3], b0, b1);
            }
        }
        __syncthreads();
    }

    // ---- epilogue ----
#pragma unroll
    for (int nt = 0; nt < NTILES; nt++) {
        int ccol = colbase + warp_n + nt * 8 + q * 2;
        float bv0 = 0.f, bv1 = 0.f;
        if (bias) { bv0 = bias[ccol]; bv1 = bias[ccol + 1]; }
#pragma unroll
        for (int mt = 0; mt < 2; mt++) {
            int r0 = rowbase + warp_m + mt * 16 + grp;
            int r1 = r0 + 8;
            float v0 = acc[mt][nt][0] + bv0;
            float v1 = acc[mt][nt][1] + bv1;
            float v2 = acc[mt][nt][2] + bv0;
            float v3 = acc[mt][nt][3] + bv1;
            if (Cin) {
                if (r0 < M) { float2 ci = *(const float2*)&Cin[(size_t)r0 * ldc + ccol]; v0 += ci.x; v1 += ci.y; }
                if (r1 < M) { float2 ci = *(const float2*)&Cin[(size_t)r1 * ldc + ccol]; v2 += ci.x; v3 += ci.y; }
            }
            if (do_relu) {
                v0 = fmaxf(v0, 0.f); v1 = fmaxf(v1, 0.f);
                v2 = fmaxf(v2, 0.f); v3 = fmaxf(v3, 0.f);
            }
            if (r0 < M) {
                float2 o = {v0, v1};
                *(float2*)&C[(size_t)r0 * ldc + ccol] = o;
                if (Cbf) *(__nv_bfloat162*)&Cbf[(size_t)r0 * ldc + ccol] = __floats2bfloat162_rn(v0, v1);
            }
            if (r1 < M) {
                float2 o = {v2, v3};
                *(float2*)&C[(size_t)r1 * ldc + ccol] = o;
                if (Cbf) *(__nv_bfloat162*)&Cbf[(size_t)r1 * ldc + ccol] = __floats2bfloat162_rn(v2, v3);
            }
        }
    }
}

// -------------------- launch --------------------
extern "C" void kernel_launch(void* const* d_in, const int* in_sizes, int n_in,
                              void* d_out, int out_size) {
    const float* x   = (const float*)d_in[0];
    const void*  ei  = d_in[1];
    const float* Wl0 = (const float*)d_in[2];
    const float* Wr0 = (const float*)d_in[3];
    const float* b0  = (const float*)d_in[4];
    const float* Wl1 = (const float*)d_in[5];
    const float* Wr1 = (const float*)d_in[6];
    const float* b1  = (const float*)d_in[7];
    const float* Wf  = (const float*)d_in[8];
    const float* bf  = (const float*)d_in[9];
    (void)n_in; (void)out_size;

    int Nn = in_sizes[0] / 128;   // 100000
    int Ee = in_sizes[1] / 2;     // 3200000

    float* out = (float*)d_out;                 // [N, 64]
    float* emb = out + (size_t)Nn * 64;         // [N, 256]

    void *p_agg, *p_h, *p_tmp, *p_hbf;
    cudaGetSymbolAddress(&p_agg, g_agg);
    cudaGetSymbolAddress(&p_h, g_h);
    cudaGetSymbolAddress(&p_tmp, g_tmp);
    cudaGetSymbolAddress(&p_hbf, g_hbf);
    float* agg = (float*)p_agg;
    float* h   = (float*)p_h;
    float* tmp = (float*)p_tmp;
    __nv_bfloat16* hbf = (__nv_bfloat16*)p_hbf;

    dim3 gemm_grid(2, (Nn + TBM - 1) / TBM);        // TBN=128, Ncol=256
    dim3 head_grid(1, (Nn + TBM - 1) / TBM);        // TBN=64,  Ncol=64

    // side stream + events (host objects; leaked, few calls ever, replays use the graph)
    cudaStream_t s2;
    cudaStreamCreateWithFlags(&s2, cudaStreamNonBlocking);
    cudaEvent_t evF1, evJ1;
    cudaEventCreateWithFlags(&evF1, cudaEventDisableTiming);
    cudaEventCreateWithFlags(&evJ1, cudaEventDisableTiming);

    // 0) dtype detect
    detect_kernel<<<1, 64>>>(ei, Nn);

    // ---- fork: t0 = x@Wl0 + b0 on s2, overlapping CSR build + agg0 on main ----
    cudaEventRecord(evF1, 0);
    cudaStreamWaitEvent(s2, evF1, 0);

    gemm_tf32_kernel<8><<<gemm_grid, 256, 0, s2>>>(
        x, 128, 128, nullptr, 0, 0, Wl0, nullptr, b0, nullptr,
        tmp, 256, nullptr, Nn, 256, 0);

    zero_count_kernel<<<(Nn + 256) / 256, 256>>>(Nn);
    hist_kernel<<<(Ee + 255) / 256, 256>>>(ei, Ee);
    scan_p1<<<SCAN_BLOCKS, SCAN_THREADS>>>(Nn);
    scan_p2<<<1, SCAN_BLOCKS>>>(Ee, Nn);
    scan_p3<<<SCAN_BLOCKS, SCAN_THREADS>>>(Nn);
    scatter_kernel<<<(Ee + 255) / 256, 256>>>(ei, Ee);
    agg_f32_kernel<<<(Nn + 7) / 8, 256>>>((const float4*)x, (float4*)agg, Nn);

    cudaEventRecord(evJ1, s2);
    cudaStreamWaitEvent(0, evJ1, 0);

    // join: h = relu(tmp + agg0@Wr0), emit bf16 mirror
    gemm_tf32_kernel<8><<<gemm_grid, 256>>>(
        agg, 128, 128, nullptr, 0, 0, Wr0, nullptr, nullptr, tmp,
        h, 256, hbf, Nn, 256, 1);

    // layer 1: agg (bf16 gather) then single fused GEMM (no tmp round-trip)
    agg_bf16_kernel<<<(Nn + 7) / 8, 256>>>(hbf, (float4*)agg, Nn);
    gemm_tf32_kernel<8><<<gemm_grid, 256>>>(
        h, 256, 256, agg, 256, 256, Wl1, Wr1, b1, nullptr,
        emb, 256, nullptr, Nn, 256, 1);

    // head: out = emb @ Wf + bf
    gemm_tf32_kernel<4><<<head_grid, 256>>>(
        emb, 256, 256, nullptr, 0, 0, Wf, nullptr, bf, nullptr,
        out, 64, nullptr, Nn, 64, 0);
}